// round 1
// baseline (speedup 1.0000x reference)
#include <cuda_runtime.h>
#include <math.h>

#define NPOS 2304
#define FEATSZ (2*2*4*128*NPOS)

// Scratch (static device allocations are the sanctioned workaround)
__device__ float g_feat2[FEATSZ];  // ping-pong feat buffer
__device__ float g_m[FEATSZ];      // graph messages
__device__ float g_z[FEATSZ];      // GRU z gate
__device__ float g_r[FEATSZ];      // GRU r gate

__device__ __forceinline__ float sigm(float x) { return 1.f / (1.f + expf(-x)); }

// ---------------------------------------------------------------------------
// Kernel 1: PPM dilated conv 3x3 + BN-style scale/bias + ReLU
// grid: (co_block=8, b*rowtile=6, mod*node=8), block 192
// Each thread: 16 out-channels x 4 rows x 1 col => 64 accumulators.
// ---------------------------------------------------------------------------
__global__ __launch_bounds__(192, 2)
void conv_kernel(const float* __restrict__ inR, const float* __restrict__ inD,
                 const float* __restrict__ wR, const float* __restrict__ sR, const float* __restrict__ bR,
                 const float* __restrict__ wD, const float* __restrict__ sD, const float* __restrict__ bD,
                 float* __restrict__ out)
{
    const int tid  = threadIdx.x;
    const int mz   = blockIdx.z;             // 0..7
    const int mod  = mz >> 2, node = mz & 3;
    const int dil  = 1 << node;              // 1,2,4,8
    const int b    = blockIdx.y / 3;
    const int rt   = blockIdx.y % 3;
    const int row0 = rt * 16;
    const int co0  = blockIdx.x * 16;

    const float* __restrict__ in = (mod ? inD : inR) + (size_t)b * 512 * NPOS;
    const float* __restrict__ W  = (mod ? wD : wR) + (size_t)node * (128 * 512 * 9);
    const float* __restrict__ sc = (mod ? sD : sR) + node * 128;
    const float* __restrict__ bi = (mod ? bD : bR) + node * 128;

    __shared__ float s_in[4][32 * 66];   // pitch 66 to break bank aliasing
    __shared__ float s_w[4][9][16];

    const int rows = 16 + 2 * dil;       // <= 32
    const int cols = 48 + 2 * dil;       // <= 64
    const int tx = tid % 48;
    const int rg = tid / 48;             // 0..3

    float acc[16][4];
#pragma unroll
    for (int i = 0; i < 16; i++)
#pragma unroll
        for (int j = 0; j < 4; j++) acc[i][j] = 0.f;

    const int nElem = 4 * rows * cols;

    for (int cc = 0; cc < 512; cc += 4) {
        // stage input tile (with halo, zero-padded)
        for (int idx = tid; idx < nElem; idx += 192) {
            int ci  = idx / (rows * cols);
            int rem = idx - ci * (rows * cols);
            int yy  = rem / cols;
            int xx  = rem - yy * cols;
            int gy  = row0 - dil + yy;
            int gx  = xx - dil;
            float v = 0.f;
            if ((unsigned)gy < 48u && (unsigned)gx < 48u)
                v = in[(size_t)(cc + ci) * NPOS + gy * 48 + gx];
            s_in[ci][yy * 66 + xx] = v;
        }
        // stage weights: 16co x 4ci x 9
        for (int idx = tid; idx < 576; idx += 192) {
            int co = idx & 15;
            int kk = (idx >> 4) % 9;
            int ci = idx / 144;
            s_w[ci][kk][co] = W[((size_t)(co0 + co) * 512 + cc + ci) * 9 + kk];
        }
        __syncthreads();

#pragma unroll
        for (int ci = 0; ci < 4; ci++) {
#pragma unroll
            for (int ky = 0; ky < 3; ky++) {
#pragma unroll
                for (int kx = 0; kx < 3; kx++) {
                    float v[4];
#pragma unroll
                    for (int rr = 0; rr < 4; rr++)
                        v[rr] = s_in[ci][(rg * 4 + rr + ky * dil) * 66 + tx + kx * dil];
#pragma unroll
                    for (int co = 0; co < 16; co++) {
                        float wv = s_w[ci][ky * 3 + kx][co];
#pragma unroll
                        for (int rr = 0; rr < 4; rr++)
                            acc[co][rr] = fmaf(wv, v[rr], acc[co][rr]);
                    }
                }
            }
        }
        __syncthreads();
    }

    // epilogue: relu(acc*scale + bias)
    float* outp = out + (size_t)(((mod * 2 + b) * 4 + node) * 128 + co0) * NPOS;
#pragma unroll
    for (int co = 0; co < 16; co++) {
        float s = sc[co0 + co], bb = bi[co0 + co];
#pragma unroll
        for (int rr = 0; rr < 4; rr++) {
            int r = row0 + rg * 4 + rr;
            float v = fmaf(acc[co][rr], s, bb);
            outp[(size_t)co * NPOS + r * 48 + tx] = fmaxf(v, 0.f);
        }
    }
}

// ---------------------------------------------------------------------------
// Kernel 2: PA cross-modal gating (2 iterations), in-place on feat
// 1 thread per (b,n,pos): consecutive threads -> consecutive pos (coalesced)
// ---------------------------------------------------------------------------
__global__ void pa_kernel(float* __restrict__ feat, const float* __restrict__ paw)
{
    int t = blockIdx.x * blockDim.x + threadIdx.x;
    if (t >= 8 * NPOS) return;
    int pos = t % NPOS;
    int bn  = t / NPOS;                        // b*4+n
    float* pr = feat + (size_t)bn * 128 * NPOS + pos;          // rgb
    float* pd = feat + (size_t)(8 + bn) * 128 * NPOS + pos;    // dep

    for (int it = 0; it < 2; it++) {
        float s0 = 0.f, s1 = 0.f;
        for (int c = 0; c < 128; c++) {
            float r = pr[(size_t)c * NPOS], d = pd[(size_t)c * NPOS];
            float df = r - d;
            s0 = fmaf(df,  __ldg(paw + c),       s0);
            s1 = fmaf(-df, __ldg(paw + 128 + c), s1);
        }
        float g0 = sigm(s0), g1 = sigm(s1);
        for (int c = 0; c < 128; c++) {
            float r = pr[(size_t)c * NPOS], d = pd[(size_t)c * NPOS];
            pr[(size_t)c * NPOS] = fmaf(d, g1, r);
            pd[(size_t)c * NPOS] = fmaf(r, g0, d);
        }
    }
}

// ---------------------------------------------------------------------------
// Kernel 3 (G1): graph edge gates + messages m
// grid: (postile=18, b=2, mod=2), block 128 (1 thread per pos)
// ---------------------------------------------------------------------------
__global__ void g1_kernel(float* __restrict__ dout, int it,
                          const float* __restrict__ wgtR, const float* __restrict__ wgtD)
{
    const float* feat = it ? g_feat2 : dout;
    int pos = blockIdx.x * 128 + threadIdx.x;
    int b = blockIdx.y, mod = blockIdx.z;
    const float* wgt = mod ? wgtD : wgtR;            // (3,128)
    size_t base = (size_t)((mod * 2 + b) * 4) * 128 * NPOS;
    const float* f = feat + base + pos;
    float* mo = g_m + base + pos;

    float s[3][4];
#pragma unroll
    for (int k = 0; k < 3; k++)
#pragma unroll
        for (int p = 0; p < 4; p++) s[k][p] = 0.f;

    for (int c = 0; c < 128; c++) {
        float w0 = __ldg(wgt + c), w1 = __ldg(wgt + 128 + c), w2 = __ldg(wgt + 256 + c);
#pragma unroll
        for (int p = 0; p < 4; p++) {
            float fv = f[(size_t)(p * 128 + c) * NPOS];
            s[0][p] = fmaf(w0, fv, s[0][p]);
            s[1][p] = fmaf(w1, fv, s[1][p]);
            s[2][p] = fmaf(w2, fv, s[2][p]);
        }
    }

    const int OI[4][3] = {{1,2,3},{0,2,3},{0,1,3},{0,1,2}};
    float sg[4][3];
#pragma unroll
    for (int i = 0; i < 4; i++)
#pragma unroll
        for (int k = 0; k < 3; k++)
            sg[i][k] = sigm(s[k][i] - s[k][OI[i][k]]);

    for (int c = 0; c < 128; c++) {
        int c3 = c % 3;
        float fv[4];
#pragma unroll
        for (int p = 0; p < 4; p++) fv[p] = f[(size_t)(p * 128 + c) * NPOS];
#pragma unroll
        for (int i = 0; i < 4; i++) {
            float msum = 0.f;
#pragma unroll
            for (int k = 0; k < 3; k++) {
                int gi = 2 * k + c3;              // (2k + c%3) % 3, range 0..6
                if (gi >= 3) gi -= 3;
                if (gi >= 3) gi -= 3;
                msum = fmaf(fv[OI[i][k]], sg[i][gi], msum);
            }
            mo[(size_t)(i * 128 + c) * NPOS] = msum;
        }
    }
}

// ---------------------------------------------------------------------------
// Kernel 4 (G2): GEMM z,r = sigmoid(W01 [256x256] @ hc [256 x pos] + b01)
// hc = [m ; feat]. grid: (mtile=4, ntile=36, mod*bn=16), block 256, 4x4/thread
// ---------------------------------------------------------------------------
__global__ __launch_bounds__(256)
void g2_kernel(float* __restrict__ dout, int it,
               const float* __restrict__ gwR, const float* __restrict__ gbR,
               const float* __restrict__ gwD, const float* __restrict__ gbD)
{
    const float* feat = it ? g_feat2 : dout;
    int zid = blockIdx.z;
    int mod = zid >> 3, bn = zid & 7;
    const float* A    = mod ? gwD : gwR;     // gates 0,1 contiguous => [256][256]
    const float* bias = mod ? gbD : gbR;     // [256] covers b0,b1
    size_t base = (size_t)(mod * 8 + bn) * 128 * NPOS;
    const float* F = feat + base;
    const float* M = g_m + base;

    int o0 = blockIdx.x * 64, col0 = blockIdx.y * 64;

    __shared__ float As[16][68];   // transposed, padded (float4-aligned rows)
    __shared__ float Bs[16][64];

    int tid = threadIdx.x;
    int to = tid >> 4, tn = tid & 15;
    float acc[4][4];
#pragma unroll
    for (int i = 0; i < 4; i++)
#pragma unroll
        for (int j = 0; j < 4; j++) acc[i][j] = 0.f;

    for (int k0 = 0; k0 < 256; k0 += 16) {
#pragma unroll
        for (int l = 0; l < 4; l++) {
            int e = tid + l * 256;
            int r = e >> 4, c = e & 15;
            As[c][r] = A[(size_t)(o0 + r) * 256 + k0 + c];
        }
#pragma unroll
        for (int l = 0; l < 4; l++) {
            int e = tid + l * 256;
            int kk = e >> 6, j = e & 63;
            int x = k0 + kk;
            Bs[kk][j] = (x < 128) ? M[(size_t)x * NPOS + col0 + j]
                                  : F[(size_t)(x - 128) * NPOS + col0 + j];
        }
        __syncthreads();
#pragma unroll
        for (int k = 0; k < 16; k++) {
            float4 a4 = *(const float4*)&As[k][to * 4];
            float4 b4 = *(const float4*)&Bs[k][tn * 4];
            float a[4] = {a4.x, a4.y, a4.z, a4.w};
            float bb[4] = {b4.x, b4.y, b4.z, b4.w};
#pragma unroll
            for (int i = 0; i < 4; i++)
#pragma unroll
                for (int j = 0; j < 4; j++)
                    acc[i][j] = fmaf(a[i], bb[j], acc[i][j]);
        }
        __syncthreads();
    }

#pragma unroll
    for (int i = 0; i < 4; i++) {
        int o = o0 + to * 4 + i;
        float bv = __ldg(bias + o);
        float* ob = (o < 128) ? (g_z + base + (size_t)o * NPOS)
                              : (g_r + base + (size_t)(o - 128) * NPOS);
#pragma unroll
        for (int j = 0; j < 4; j++) {
            int col = col0 + tn * 4 + j;
            ob[col] = sigm(acc[i][j] + bv);
        }
    }
}

// ---------------------------------------------------------------------------
// Kernel 5 (G3): GEMM cand = tanh(W2 @ [m ; feat*r] + b2), fused GRU update:
//   dst = gamma*(feat*(1-z) + cand*z) + feat
// grid: (mtile=2, ntile=36, mod*bn=16), block 256
// ---------------------------------------------------------------------------
__global__ __launch_bounds__(256)
void g3_kernel(float* __restrict__ dout, int it,
               const float* __restrict__ gwR, const float* __restrict__ gbR,
               const float* __restrict__ gwD, const float* __restrict__ gbD,
               const float* __restrict__ gamR, const float* __restrict__ gamD)
{
    const float* feat = it ? g_feat2 : dout;
    float* dst        = it ? dout : g_feat2;
    int zid = blockIdx.z;
    int mod = zid >> 3, bn = zid & 7;
    const float* A    = (mod ? gwD : gwR) + 2 * 128 * 256;   // gate 2
    const float* bias = (mod ? gbD : gbR) + 2 * 128;
    float gam = mod ? __ldg(gamD) : __ldg(gamR);
    size_t base = (size_t)(mod * 8 + bn) * 128 * NPOS;
    const float* F = feat + base;
    const float* M = g_m + base;
    const float* R = g_r + base;

    int o0 = blockIdx.x * 64, col0 = blockIdx.y * 64;

    __shared__ float As[16][68];
    __shared__ float Bs[16][64];

    int tid = threadIdx.x;
    int to = tid >> 4, tn = tid & 15;
    float acc[4][4];
#pragma unroll
    for (int i = 0; i < 4; i++)
#pragma unroll
        for (int j = 0; j < 4; j++) acc[i][j] = 0.f;

    for (int k0 = 0; k0 < 256; k0 += 16) {
#pragma unroll
        for (int l = 0; l < 4; l++) {
            int e = tid + l * 256;
            int r = e >> 4, c = e & 15;
            As[c][r] = A[(size_t)(o0 + r) * 256 + k0 + c];
        }
#pragma unroll
        for (int l = 0; l < 4; l++) {
            int e = tid + l * 256;
            int kk = e >> 6, j = e & 63;
            int x = k0 + kk;
            float v;
            if (x < 128) v = M[(size_t)x * NPOS + col0 + j];
            else {
                size_t idx = (size_t)(x - 128) * NPOS + col0 + j;
                v = F[idx] * R[idx];
            }
            Bs[kk][j] = v;
        }
        __syncthreads();
#pragma unroll
        for (int k = 0; k < 16; k++) {
            float4 a4 = *(const float4*)&As[k][to * 4];
            float4 b4 = *(const float4*)&Bs[k][tn * 4];
            float a[4] = {a4.x, a4.y, a4.z, a4.w};
            float bb[4] = {b4.x, b4.y, b4.z, b4.w};
#pragma unroll
            for (int i = 0; i < 4; i++)
#pragma unroll
                for (int j = 0; j < 4; j++)
                    acc[i][j] = fmaf(a[i], bb[j], acc[i][j]);
        }
        __syncthreads();
    }

#pragma unroll
    for (int i = 0; i < 4; i++) {
        int o = o0 + to * 4 + i;
        float bv = __ldg(bias + o);
#pragma unroll
        for (int j = 0; j < 4; j++) {
            int col = col0 + tn * 4 + j;
            size_t idx = base + (size_t)o * NPOS + col;
            float cand = tanhf(acc[i][j] + bv);
            float z = g_z[idx];
            float f = feat[idx];
            dst[idx] = fmaf(gam, fmaf(f, 1.f - z, cand * z), f);
        }
    }
}

// ---------------------------------------------------------------------------
extern "C" void kernel_launch(void* const* d_in, const int* in_sizes, int n_in,
                              void* d_out, int out_size)
{
    const float* feat_rgb = (const float*)d_in[0];
    const float* feat_dep = (const float*)d_in[1];
    const float* ppm_w_r  = (const float*)d_in[2];
    const float* ppm_s_r  = (const float*)d_in[3];
    const float* ppm_b_r  = (const float*)d_in[4];
    const float* ppm_w_d  = (const float*)d_in[5];
    const float* ppm_s_d  = (const float*)d_in[6];
    const float* ppm_b_d  = (const float*)d_in[7];
    const float* pa_w     = (const float*)d_in[8];
    const float* wgt_r    = (const float*)d_in[9];
    const float* gruw_r   = (const float*)d_in[10];
    const float* grub_r   = (const float*)d_in[11];
    const float* gam_r    = (const float*)d_in[12];
    const float* wgt_d    = (const float*)d_in[13];
    const float* gruw_d   = (const float*)d_in[14];
    const float* grub_d   = (const float*)d_in[15];
    const float* gam_d    = (const float*)d_in[16];
    float* out = (float*)d_out;

    conv_kernel<<<dim3(8, 6, 8), 192>>>(feat_rgb, feat_dep,
                                        ppm_w_r, ppm_s_r, ppm_b_r,
                                        ppm_w_d, ppm_s_d, ppm_b_d, out);
    pa_kernel<<<72, 256>>>(out, pa_w);
    for (int it = 0; it < 2; it++) {
        g1_kernel<<<dim3(18, 2, 2), 128>>>(out, it, wgt_r, wgt_d);
        g2_kernel<<<dim3(4, 36, 16), 256>>>(out, it, gruw_r, grub_r, gruw_d, grub_d);
        g3_kernel<<<dim3(2, 36, 16), 256>>>(out, it, gruw_r, grub_r, gruw_d, grub_d,
                                            gam_r, gam_d);
    }
}

// round 4
// speedup vs baseline: 2.4494x; 2.4494x over previous
#include <cuda_runtime.h>
#include <math.h>
#include <stdint.h>

#define NPOS 2304
#define FEATSZ (2*2*4*128*NPOS)

// Scratch
__device__ float g_feat2[FEATSZ];
__device__ float g_m[FEATSZ];
__device__ float g_z[FEATSZ];
__device__ float g_r[FEATSZ];
__device__ float g_wt[2*4*9*128*512];   // [mn][tap][co][ci], tf32-rounded

__device__ __forceinline__ float sigm(float x) { return 1.f / (1.f + expf(-x)); }

// cvt.rna.tf32.f32 requires a b32 destination register
__device__ __forceinline__ uint32_t tf32r(float v) {
    uint32_t o;
    asm("cvt.rna.tf32.f32 %0, %1;" : "=r"(o) : "f"(v));
    return o;
}

// m16n8k8 tf32 mma (sm_80 baseline feature, compiles under compute_100)
__device__ __forceinline__ void mma_tf32(float* c, const uint32_t* a, const uint32_t* b) {
    asm volatile(
        "mma.sync.aligned.m16n8k8.row.col.f32.tf32.tf32.f32 "
        "{%0,%1,%2,%3}, {%4,%5,%6,%7}, {%8,%9}, {%0,%1,%2,%3};"
        : "+f"(c[0]), "+f"(c[1]), "+f"(c[2]), "+f"(c[3])
        : "r"(a[0]), "r"(a[1]), "r"(a[2]), "r"(a[3]), "r"(b[0]), "r"(b[1]));
}

// ---------------------------------------------------------------------------
// Prep: transpose weights to [mn][tap][co][ci], tf32-rounded
// ---------------------------------------------------------------------------
__global__ void wt_prep_kernel(const float* __restrict__ wR, const float* __restrict__ wD)
{
    int e = blockIdx.x * 256 + threadIdx.x;
    if (e >= 2*4*9*128*512) return;
    int ci = e & 511;
    int r = e >> 9;
    int co = r & 127; r >>= 7;
    int tap = r % 9; r /= 9;
    int node = r & 3;
    int mod = r >> 2;
    const float* w = mod ? wD : wR;
    g_wt[e] = __uint_as_float(tf32r(w[((size_t)(node*128 + co)*512 + ci)*9 + tap]));
}

// ---------------------------------------------------------------------------
// Conv via mma.sync tf32 implicit GEMM.
// grid: (48 = b*24 + rowpair, 8 = mod*4+node), 256 threads (8 warps: 4m x 2n)
// CTA tile: 128 co x 96 pos, K = 144 stages of 32.
// ---------------------------------------------------------------------------
#define APITCH 36
#define BPITCH 104
#define A_BUF (128*APITCH)          // floats
#define B_BUF (32*BPITCH)
#define CONV_SMEM ((2*A_BUF + 2*B_BUF)*4)

__global__ __launch_bounds__(256)
void conv_mma_kernel(const float* __restrict__ inR, const float* __restrict__ inD,
                     const float* __restrict__ sR, const float* __restrict__ bR,
                     const float* __restrict__ sD, const float* __restrict__ bD,
                     float* __restrict__ out)
{
    extern __shared__ float smem[];
    float* As[2] = { smem,               smem + A_BUF };
    float* Bs[2] = { smem + 2*A_BUF,     smem + 2*A_BUF + B_BUF };

    const int tid = threadIdx.x;
    const int lane = tid & 31;
    const int wid = tid >> 5;
    const int wm = wid & 3;            // warp m: co block of 32
    const int wn = wid >> 2;           // warp n: pos block of 48

    const int mn   = blockIdx.y;
    const int mod  = mn >> 2, node = mn & 3;
    const int dil  = 1 << node;
    const int b    = blockIdx.x / 24;
    const int y0   = (blockIdx.x % 24) * 2;

    const float* __restrict__ in = (mod ? inD : inR) + (size_t)b * 512 * NPOS;
    const float* __restrict__ Wt = g_wt + (size_t)mn * 9 * 128 * 512;

    // staging maps
    const int arow = tid >> 1;                  // 0..127
    const int ahalf = (tid & 1) * 16;
    const int tx  = tid & 31;                   // pos lane
    const int grp = tid >> 5;                   // ci group 0..7

    float acc[2][6][4];
#pragma unroll
    for (int i = 0; i < 2; i++)
#pragma unroll
        for (int j = 0; j < 6; j++)
#pragma unroll
            for (int k = 0; k < 4; k++) acc[i][j][k] = 0.f;

    // ---- stage function ----
#define STAGE(S, BUF) do {                                                    \
    int tap_ = (S) >> 4;                                                      \
    int cc_  = ((S) & 15) * 32;                                               \
    int dy_  = (tap_ / 3 - 1) * dil;                                          \
    int dx_  = (tap_ % 3 - 1) * dil;                                          \
    const float* wrow_ = Wt + ((size_t)tap_ * 128 + arow) * 512 + cc_ + ahalf;\
    float* A_ = As[BUF]; float* B_ = Bs[BUF];                                 \
    _Pragma("unroll")                                                         \
    for (int j = 0; j < 4; j++) {                                             \
        float4 v = *(const float4*)(wrow_ + j * 4);                           \
        *(float4*)(A_ + arow * APITCH + ahalf + j * 4) = v;                   \
    }                                                                         \
    _Pragma("unroll")                                                         \
    for (int pb = 0; pb < 3; pb++) {                                          \
        int posl = tx + 32 * pb;                                              \
        int ry = posl / 48;                                                   \
        int x  = posl - ry * 48;                                              \
        int xs = x + dx_, ys = y0 + ry + dy_;                                 \
        bool ok = ((unsigned)xs < 48u) && ((unsigned)ys < 48u);               \
        int goff = ys * 48 + xs;                                              \
        _Pragma("unroll")                                                     \
        for (int cb = 0; cb < 4; cb++) {                                      \
            int ci = grp + 8 * cb;                                            \
            float v = 0.f;                                                    \
            if (ok) v = in[(size_t)(cc_ + ci) * NPOS + goff];                 \
            B_[ci * BPITCH + posl] = __uint_as_float(tf32r(v));               \
        }                                                                     \
    }                                                                         \
} while (0)

    STAGE(0, 0);
    __syncthreads();

    const int m0 = wm * 32;
    const int n0 = wn * 48;
    const int arow0 = lane >> 2;      // 0..7
    const int acol0 = lane & 3;
    const int brow0 = lane & 3;
    const int bcol0 = lane >> 2;

    for (int s = 0; s < 144; s++) {
        int buf = s & 1;
        if (s + 1 < 144) STAGE(s + 1, buf ^ 1);

        const float* A_ = As[buf];
        const float* B_ = Bs[buf];
#pragma unroll
        for (int k0 = 0; k0 < 32; k0 += 8) {
            uint32_t afr[2][4];
#pragma unroll
            for (int mt = 0; mt < 2; mt++) {
                int r = m0 + mt * 16 + arow0;
                afr[mt][0] = __float_as_uint(A_[r * APITCH + k0 + acol0]);
                afr[mt][1] = __float_as_uint(A_[(r + 8) * APITCH + k0 + acol0]);
                afr[mt][2] = __float_as_uint(A_[r * APITCH + k0 + acol0 + 4]);
                afr[mt][3] = __float_as_uint(A_[(r + 8) * APITCH + k0 + acol0 + 4]);
            }
#pragma unroll
            for (int nt = 0; nt < 6; nt++) {
                uint32_t bfr[2];
                int ncol = n0 + nt * 8 + bcol0;
                bfr[0] = __float_as_uint(B_[(k0 + brow0) * BPITCH + ncol]);
                bfr[1] = __float_as_uint(B_[(k0 + brow0 + 4) * BPITCH + ncol]);
                mma_tf32(acc[0][nt], afr[0], bfr);
                mma_tf32(acc[1][nt], afr[1], bfr);
            }
        }
        __syncthreads();
    }

    // epilogue: relu(acc*scale + bias), float2 stores
    const float* sc = (mod ? sD : sR) + node * 128;
    const float* bi = (mod ? bD : bR) + node * 128;
    float* outp = out + ((size_t)((mod * 2 + b) * 4 + node) * 128) * NPOS + y0 * 48;

#pragma unroll
    for (int mt = 0; mt < 2; mt++) {
#pragma unroll
        for (int half = 0; half < 2; half++) {
            int co = m0 + mt * 16 + half * 8 + (lane >> 2);
            float s = __ldg(sc + co), bb = __ldg(bi + co);
            float* orow = outp + (size_t)co * NPOS;
#pragma unroll
            for (int nt = 0; nt < 6; nt++) {
                int pos = n0 + nt * 8 + (lane & 3) * 2;
                float v0 = fmaxf(fmaf(acc[mt][nt][half * 2 + 0], s, bb), 0.f);
                float v1 = fmaxf(fmaf(acc[mt][nt][half * 2 + 1], s, bb), 0.f);
                *(float2*)(orow + pos) = make_float2(v0, v1);
            }
        }
    }
#undef STAGE
}

// ---------------------------------------------------------------------------
// Kernel 2: PA cross-modal gating
// ---------------------------------------------------------------------------
__global__ void pa_kernel(float* __restrict__ feat, const float* __restrict__ paw)
{
    int t = blockIdx.x * blockDim.x + threadIdx.x;
    if (t >= 8 * NPOS) return;
    int pos = t % NPOS;
    int bn  = t / NPOS;
    float* pr = feat + (size_t)bn * 128 * NPOS + pos;
    float* pd = feat + (size_t)(8 + bn) * 128 * NPOS + pos;

    for (int it = 0; it < 2; it++) {
        float s0 = 0.f, s1 = 0.f;
        for (int c = 0; c < 128; c++) {
            float r = pr[(size_t)c * NPOS], d = pd[(size_t)c * NPOS];
            float df = r - d;
            s0 = fmaf(df,  __ldg(paw + c),       s0);
            s1 = fmaf(-df, __ldg(paw + 128 + c), s1);
        }
        float g0 = sigm(s0), g1 = sigm(s1);
        for (int c = 0; c < 128; c++) {
            float r = pr[(size_t)c * NPOS], d = pd[(size_t)c * NPOS];
            pr[(size_t)c * NPOS] = fmaf(d, g1, r);
            pd[(size_t)c * NPOS] = fmaf(r, g0, d);
        }
    }
}

// ---------------------------------------------------------------------------
// Kernel 3 (G1): graph edge gates + messages
// ---------------------------------------------------------------------------
__global__ void g1_kernel(float* __restrict__ dout, int it,
                          const float* __restrict__ wgtR, const float* __restrict__ wgtD)
{
    const float* feat = it ? g_feat2 : dout;
    int pos = blockIdx.x * 128 + threadIdx.x;
    int b = blockIdx.y, mod = blockIdx.z;
    const float* wgt = mod ? wgtD : wgtR;
    size_t base = (size_t)((mod * 2 + b) * 4) * 128 * NPOS;
    const float* f = feat + base + pos;
    float* mo = g_m + base + pos;

    float s[3][4];
#pragma unroll
    for (int k = 0; k < 3; k++)
#pragma unroll
        for (int p = 0; p < 4; p++) s[k][p] = 0.f;

    for (int c = 0; c < 128; c++) {
        float w0 = __ldg(wgt + c), w1 = __ldg(wgt + 128 + c), w2 = __ldg(wgt + 256 + c);
#pragma unroll
        for (int p = 0; p < 4; p++) {
            float fv = f[(size_t)(p * 128 + c) * NPOS];
            s[0][p] = fmaf(w0, fv, s[0][p]);
            s[1][p] = fmaf(w1, fv, s[1][p]);
            s[2][p] = fmaf(w2, fv, s[2][p]);
        }
    }

    const int OI[4][3] = {{1,2,3},{0,2,3},{0,1,3},{0,1,2}};
    float sg[4][3];
#pragma unroll
    for (int i = 0; i < 4; i++)
#pragma unroll
        for (int k = 0; k < 3; k++)
            sg[i][k] = sigm(s[k][i] - s[k][OI[i][k]]);

    for (int c = 0; c < 128; c++) {
        int c3 = c % 3;
        float fv[4];
#pragma unroll
        for (int p = 0; p < 4; p++) fv[p] = f[(size_t)(p * 128 + c) * NPOS];
#pragma unroll
        for (int i = 0; i < 4; i++) {
            float msum = 0.f;
#pragma unroll
            for (int k = 0; k < 3; k++) {
                int gi = 2 * k + c3;
                if (gi >= 3) gi -= 3;
                if (gi >= 3) gi -= 3;
                msum = fmaf(fv[OI[i][k]], sg[i][gi], msum);
            }
            mo[(size_t)(i * 128 + c) * NPOS] = msum;
        }
    }
}

// ---------------------------------------------------------------------------
// Kernel 4 (G2): z,r GEMM
// ---------------------------------------------------------------------------
__global__ __launch_bounds__(256)
void g2_kernel(float* __restrict__ dout, int it,
               const float* __restrict__ gwR, const float* __restrict__ gbR,
               const float* __restrict__ gwD, const float* __restrict__ gbD)
{
    const float* feat = it ? g_feat2 : dout;
    int zid = blockIdx.z;
    int mod = zid >> 3, bn = zid & 7;
    const float* A    = mod ? gwD : gwR;
    const float* bias = mod ? gbD : gbR;
    size_t base = (size_t)(mod * 8 + bn) * 128 * NPOS;
    const float* F = feat + base;
    const float* M = g_m + base;

    int o0 = blockIdx.x * 64, col0 = blockIdx.y * 64;

    __shared__ float As[16][68];
    __shared__ float Bs[16][64];

    int tid = threadIdx.x;
    int to = tid >> 4, tn = tid & 15;
    float acc[4][4];
#pragma unroll
    for (int i = 0; i < 4; i++)
#pragma unroll
        for (int j = 0; j < 4; j++) acc[i][j] = 0.f;

    for (int k0 = 0; k0 < 256; k0 += 16) {
#pragma unroll
        for (int l = 0; l < 4; l++) {
            int e = tid + l * 256;
            int r = e >> 4, c = e & 15;
            As[c][r] = A[(size_t)(o0 + r) * 256 + k0 + c];
        }
#pragma unroll
        for (int l = 0; l < 4; l++) {
            int e = tid + l * 256;
            int kk = e >> 6, j = e & 63;
            int x = k0 + kk;
            Bs[kk][j] = (x < 128) ? M[(size_t)x * NPOS + col0 + j]
                                  : F[(size_t)(x - 128) * NPOS + col0 + j];
        }
        __syncthreads();
#pragma unroll
        for (int k = 0; k < 16; k++) {
            float4 a4 = *(const float4*)&As[k][to * 4];
            float4 b4 = *(const float4*)&Bs[k][tn * 4];
            float a[4] = {a4.x, a4.y, a4.z, a4.w};
            float bb[4] = {b4.x, b4.y, b4.z, b4.w};
#pragma unroll
            for (int i = 0; i < 4; i++)
#pragma unroll
                for (int j = 0; j < 4; j++)
                    acc[i][j] = fmaf(a[i], bb[j], acc[i][j]);
        }
        __syncthreads();
    }

#pragma unroll
    for (int i = 0; i < 4; i++) {
        int o = o0 + to * 4 + i;
        float bv = __ldg(bias + o);
        float* ob = (o < 128) ? (g_z + base + (size_t)o * NPOS)
                              : (g_r + base + (size_t)(o - 128) * NPOS);
#pragma unroll
        for (int j = 0; j < 4; j++) {
            int col = col0 + tn * 4 + j;
            ob[col] = sigm(acc[i][j] + bv);
        }
    }
}

// ---------------------------------------------------------------------------
// Kernel 5 (G3): cand GEMM + fused GRU update
// ---------------------------------------------------------------------------
__global__ __launch_bounds__(256)
void g3_kernel(float* __restrict__ dout, int it,
               const float* __restrict__ gwR, const float* __restrict__ gbR,
               const float* __restrict__ gwD, const float* __restrict__ gbD,
               const float* __restrict__ gamR, const float* __restrict__ gamD)
{
    const float* feat = it ? g_feat2 : dout;
    float* dst        = it ? dout : g_feat2;
    int zid = blockIdx.z;
    int mod = zid >> 3, bn = zid & 7;
    const float* A    = (mod ? gwD : gwR) + 2 * 128 * 256;
    const float* bias = (mod ? gbD : gbR) + 2 * 128;
    float gam = mod ? __ldg(gamD) : __ldg(gamR);
    size_t base = (size_t)(mod * 8 + bn) * 128 * NPOS;
    const float* F = feat + base;
    const float* M = g_m + base;
    const float* R = g_r + base;

    int o0 = blockIdx.x * 64, col0 = blockIdx.y * 64;

    __shared__ float As[16][68];
    __shared__ float Bs[16][64];

    int tid = threadIdx.x;
    int to = tid >> 4, tn = tid & 15;
    float acc[4][4];
#pragma unroll
    for (int i = 0; i < 4; i++)
#pragma unroll
        for (int j = 0; j < 4; j++) acc[i][j] = 0.f;

    for (int k0 = 0; k0 < 256; k0 += 16) {
#pragma unroll
        for (int l = 0; l < 4; l++) {
            int e = tid + l * 256;
            int r = e >> 4, c = e & 15;
            As[c][r] = A[(size_t)(o0 + r) * 256 + k0 + c];
        }
#pragma unroll
        for (int l = 0; l < 4; l++) {
            int e = tid + l * 256;
            int kk = e >> 6, j = e & 63;
            int x = k0 + kk;
            float v;
            if (x < 128) v = M[(size_t)x * NPOS + col0 + j];
            else {
                size_t idx = (size_t)(x - 128) * NPOS + col0 + j;
                v = F[idx] * R[idx];
            }
            Bs[kk][j] = v;
        }
        __syncthreads();
#pragma unroll
        for (int k = 0; k < 16; k++) {
            float4 a4 = *(const float4*)&As[k][to * 4];
            float4 b4 = *(const float4*)&Bs[k][tn * 4];
            float a[4] = {a4.x, a4.y, a4.z, a4.w};
            float bb[4] = {b4.x, b4.y, b4.z, b4.w};
#pragma unroll
            for (int i = 0; i < 4; i++)
#pragma unroll
                for (int j = 0; j < 4; j++)
                    acc[i][j] = fmaf(a[i], bb[j], acc[i][j]);
        }
        __syncthreads();
    }

#pragma unroll
    for (int i = 0; i < 4; i++) {
        int o = o0 + to * 4 + i;
        float bv = __ldg(bias + o);
#pragma unroll
        for (int j = 0; j < 4; j++) {
            int col = col0 + tn * 4 + j;
            size_t idx = base + (size_t)o * NPOS + col;
            float cand = tanhf(acc[i][j] + bv);
            float z = g_z[idx];
            float f = feat[idx];
            dst[idx] = fmaf(gam, fmaf(f, 1.f - z, cand * z), f);
        }
    }
}

// ---------------------------------------------------------------------------
extern "C" void kernel_launch(void* const* d_in, const int* in_sizes, int n_in,
                              void* d_out, int out_size)
{
    const float* feat_rgb = (const float*)d_in[0];
    const float* feat_dep = (const float*)d_in[1];
    const float* ppm_w_r  = (const float*)d_in[2];
    const float* ppm_s_r  = (const float*)d_in[3];
    const float* ppm_b_r  = (const float*)d_in[4];
    const float* ppm_w_d  = (const float*)d_in[5];
    const float* ppm_s_d  = (const float*)d_in[6];
    const float* ppm_b_d  = (const float*)d_in[7];
    const float* pa_w     = (const float*)d_in[8];
    const float* wgt_r    = (const float*)d_in[9];
    const float* gruw_r   = (const float*)d_in[10];
    const float* grub_r   = (const float*)d_in[11];
    const float* gam_r    = (const float*)d_in[12];
    const float* wgt_d    = (const float*)d_in[13];
    const float* gruw_d   = (const float*)d_in[14];
    const float* grub_d   = (const float*)d_in[15];
    const float* gam_d    = (const float*)d_in[16];
    float* out = (float*)d_out;

    cudaFuncSetAttribute(conv_mma_kernel,
                         cudaFuncAttributeMaxDynamicSharedMemorySize, CONV_SMEM);

    wt_prep_kernel<<<(2*4*9*128*512 + 255) / 256, 256>>>(ppm_w_r, ppm_w_d);
    conv_mma_kernel<<<dim3(48, 8), 256, CONV_SMEM>>>(feat_rgb, feat_dep,
                                                     ppm_s_r, ppm_b_r,
                                                     ppm_s_d, ppm_b_d, out);
    pa_kernel<<<72, 256>>>(out, pa_w);
    for (int it = 0; it < 2; it++) {
        g1_kernel<<<dim3(18, 2, 2), 128>>>(out, it, wgt_r, wgt_d);
        g2_kernel<<<dim3(4, 36, 16), 256>>>(out, it, gruw_r, grub_r, gruw_d, grub_d);
        g3_kernel<<<dim3(2, 36, 16), 256>>>(out, it, gruw_r, grub_r, gruw_d, grub_d,
                                            gam_r, gam_d);
    }
}

// round 6
// speedup vs baseline: 3.3661x; 1.3742x over previous
#include <cuda_runtime.h>
#include <math.h>
#include <stdint.h>

#define NPOS 2304
#define FEATSZ (2*2*4*128*NPOS)

// Scratch
__device__ float g_feat2[FEATSZ];
__device__ float g_m[FEATSZ];
__device__ float g_z[FEATSZ];
__device__ float g_r[FEATSZ];
__device__ float g_wt[2*4*9*128*512];   // conv weights [mn][tap][co][ci], tf32-rounded
__device__ float g_gw[2*3*128*256];     // gru weights  [mod][gate][o][k], tf32-rounded
__device__ float g_gate[2*2*12*NPOS];   // edge gates   [modb][i*3+k][pos]

__device__ __forceinline__ float sigm(float x) { return 1.f / (1.f + expf(-x)); }

__device__ __forceinline__ uint32_t tf32r(float v) {
    uint32_t o;
    asm("cvt.rna.tf32.f32 %0, %1;" : "=r"(o) : "f"(v));
    return o;
}

__device__ __forceinline__ void mma_tf32(float* c, const uint32_t* a, const uint32_t* b) {
    asm volatile(
        "mma.sync.aligned.m16n8k8.row.col.f32.tf32.tf32.f32 "
        "{%0,%1,%2,%3}, {%4,%5,%6,%7}, {%8,%9}, {%0,%1,%2,%3};"
        : "+f"(c[0]), "+f"(c[1]), "+f"(c[2]), "+f"(c[3])
        : "r"(a[0]), "r"(a[1]), "r"(a[2]), "r"(a[3]), "r"(b[0]), "r"(b[1]));
}

// ---------------------------------------------------------------------------
// Prep kernels: tf32-round weights
// ---------------------------------------------------------------------------
__global__ void wt_prep_kernel(const float* __restrict__ wR, const float* __restrict__ wD)
{
    int e = blockIdx.x * 256 + threadIdx.x;
    if (e >= 2*4*9*128*512) return;
    int ci = e & 511;
    int r = e >> 9;
    int co = r & 127; r >>= 7;
    int tap = r % 9; r /= 9;
    int node = r & 3;
    int mod = r >> 2;
    const float* w = mod ? wD : wR;
    g_wt[e] = __uint_as_float(tf32r(w[((size_t)(node*128 + co)*512 + ci)*9 + tap]));
}

__global__ void gw_prep_kernel(const float* __restrict__ gwR, const float* __restrict__ gwD)
{
    int e = blockIdx.x * 256 + threadIdx.x;
    if (e >= 2*3*128*256) return;
    int mod = e / (3*128*256);
    int x   = e % (3*128*256);
    const float* w = mod ? gwD : gwR;
    g_gw[e] = __uint_as_float(tf32r(w[x]));
}

// ---------------------------------------------------------------------------
// Conv via mma.sync tf32 implicit GEMM. (unchanged from R4 — proven)
// ---------------------------------------------------------------------------
#define APITCH 36
#define BPITCH 104
#define A_BUF (128*APITCH)
#define B_BUF (32*BPITCH)
#define CONV_SMEM ((2*A_BUF + 2*B_BUF)*4)

__global__ __launch_bounds__(256)
void conv_mma_kernel(const float* __restrict__ inR, const float* __restrict__ inD,
                     const float* __restrict__ sR, const float* __restrict__ bR,
                     const float* __restrict__ sD, const float* __restrict__ bD,
                     float* __restrict__ out)
{
    extern __shared__ float smem[];
    float* As[2] = { smem,           smem + A_BUF };
    float* Bs[2] = { smem + 2*A_BUF, smem + 2*A_BUF + B_BUF };

    const int tid = threadIdx.x;
    const int lane = tid & 31;
    const int wid = tid >> 5;
    const int wm = wid & 3;
    const int wn = wid >> 2;

    const int mn   = blockIdx.y;
    const int mod  = mn >> 2, node = mn & 3;
    const int dil  = 1 << node;
    const int b    = blockIdx.x / 24;
    const int y0   = (blockIdx.x % 24) * 2;

    const float* __restrict__ in = (mod ? inD : inR) + (size_t)b * 512 * NPOS;
    const float* __restrict__ Wt = g_wt + (size_t)mn * 9 * 128 * 512;

    const int arow = tid >> 1;
    const int ahalf = (tid & 1) * 16;
    const int tx  = tid & 31;
    const int grp = tid >> 5;

    float acc[2][6][4];
#pragma unroll
    for (int i = 0; i < 2; i++)
#pragma unroll
        for (int j = 0; j < 6; j++)
#pragma unroll
            for (int k = 0; k < 4; k++) acc[i][j][k] = 0.f;

#define STAGE(S, BUF) do {                                                    \
    int tap_ = (S) >> 4;                                                      \
    int cc_  = ((S) & 15) * 32;                                               \
    int dy_  = (tap_ / 3 - 1) * dil;                                          \
    int dx_  = (tap_ % 3 - 1) * dil;                                          \
    const float* wrow_ = Wt + ((size_t)tap_ * 128 + arow) * 512 + cc_ + ahalf;\
    float* A_ = As[BUF]; float* B_ = Bs[BUF];                                 \
    _Pragma("unroll")                                                         \
    for (int j = 0; j < 4; j++) {                                             \
        float4 v = *(const float4*)(wrow_ + j * 4);                           \
        *(float4*)(A_ + arow * APITCH + ahalf + j * 4) = v;                   \
    }                                                                         \
    _Pragma("unroll")                                                         \
    for (int pb = 0; pb < 3; pb++) {                                          \
        int posl = tx + 32 * pb;                                              \
        int ry = posl / 48;                                                   \
        int x  = posl - ry * 48;                                              \
        int xs = x + dx_, ys = y0 + ry + dy_;                                 \
        bool ok = ((unsigned)xs < 48u) && ((unsigned)ys < 48u);               \
        int goff = ys * 48 + xs;                                              \
        _Pragma("unroll")                                                     \
        for (int cb = 0; cb < 4; cb++) {                                      \
            int ci = grp + 8 * cb;                                            \
            float v = 0.f;                                                    \
            if (ok) v = in[(size_t)(cc_ + ci) * NPOS + goff];                 \
            B_[ci * BPITCH + posl] = __uint_as_float(tf32r(v));               \
        }                                                                     \
    }                                                                         \
} while (0)

    STAGE(0, 0);
    __syncthreads();

    const int m0 = wm * 32;
    const int n0 = wn * 48;
    const int arow0 = lane >> 2;
    const int acol0 = lane & 3;
    const int brow0 = lane & 3;
    const int bcol0 = lane >> 2;

    for (int s = 0; s < 144; s++) {
        int buf = s & 1;
        if (s + 1 < 144) STAGE(s + 1, buf ^ 1);

        const float* A_ = As[buf];
        const float* B_ = Bs[buf];
#pragma unroll
        for (int k0 = 0; k0 < 32; k0 += 8) {
            uint32_t afr[2][4];
#pragma unroll
            for (int mt = 0; mt < 2; mt++) {
                int r = m0 + mt * 16 + arow0;
                afr[mt][0] = __float_as_uint(A_[r * APITCH + k0 + acol0]);
                afr[mt][1] = __float_as_uint(A_[(r + 8) * APITCH + k0 + acol0]);
                afr[mt][2] = __float_as_uint(A_[r * APITCH + k0 + acol0 + 4]);
                afr[mt][3] = __float_as_uint(A_[(r + 8) * APITCH + k0 + acol0 + 4]);
            }
#pragma unroll
            for (int nt = 0; nt < 6; nt++) {
                uint32_t bfr[2];
                int ncol = n0 + nt * 8 + bcol0;
                bfr[0] = __float_as_uint(B_[(k0 + brow0) * BPITCH + ncol]);
                bfr[1] = __float_as_uint(B_[(k0 + brow0 + 4) * BPITCH + ncol]);
                mma_tf32(acc[0][nt], afr[0], bfr);
                mma_tf32(acc[1][nt], afr[1], bfr);
            }
        }
        __syncthreads();
    }

    const float* sc = (mod ? sD : sR) + node * 128;
    const float* bi = (mod ? bD : bR) + node * 128;
    float* outp = out + ((size_t)((mod * 2 + b) * 4 + node) * 128) * NPOS + y0 * 48;

#pragma unroll
    for (int mt = 0; mt < 2; mt++) {
#pragma unroll
        for (int half = 0; half < 2; half++) {
            int co = m0 + mt * 16 + half * 8 + (lane >> 2);
            float s = __ldg(sc + co), bb = __ldg(bi + co);
            float* orow = outp + (size_t)co * NPOS;
#pragma unroll
            for (int nt = 0; nt < 6; nt++) {
                int pos = n0 + nt * 8 + (lane & 3) * 2;
                float v0 = fmaxf(fmaf(acc[mt][nt][half * 2 + 0], s, bb), 0.f);
                float v1 = fmaxf(fmaf(acc[mt][nt][half * 2 + 1], s, bb), 0.f);
                *(float2*)(orow + pos) = make_float2(v0, v1);
            }
        }
    }
#undef STAGE
}

// ---------------------------------------------------------------------------
// Kernel 2: PA cross-modal gating
// ---------------------------------------------------------------------------
__global__ void pa_kernel(float* __restrict__ feat, const float* __restrict__ paw)
{
    int t = blockIdx.x * blockDim.x + threadIdx.x;
    if (t >= 8 * NPOS) return;
    int pos = t % NPOS;
    int bn  = t / NPOS;
    float* pr = feat + (size_t)bn * 128 * NPOS + pos;
    float* pd = feat + (size_t)(8 + bn) * 128 * NPOS + pos;

    for (int it = 0; it < 2; it++) {
        float s0 = 0.f, s1 = 0.f;
        for (int c = 0; c < 128; c++) {
            float r = pr[(size_t)c * NPOS], d = pd[(size_t)c * NPOS];
            float df = r - d;
            s0 = fmaf(df,  __ldg(paw + c),       s0);
            s1 = fmaf(-df, __ldg(paw + 128 + c), s1);
        }
        float g0 = sigm(s0), g1 = sigm(s1);
        for (int c = 0; c < 128; c++) {
            float r = pr[(size_t)c * NPOS], d = pd[(size_t)c * NPOS];
            pr[(size_t)c * NPOS] = fmaf(d, g1, r);
            pd[(size_t)c * NPOS] = fmaf(r, g0, d);
        }
    }
}

// ---------------------------------------------------------------------------
// g1a: edge gates. block 256 = 64 pos x 4 channel-splits; smem reduction.
// grid: (36, 2, 2)
// ---------------------------------------------------------------------------
__global__ __launch_bounds__(256)
void g1a_kernel(const float* __restrict__ dout, int it,
                const float* __restrict__ wgtR, const float* __restrict__ wgtD)
{
    const float* feat = it ? g_feat2 : dout;
    const int pl = threadIdx.x & 63;
    const int cs = threadIdx.x >> 6;
    const int pos = blockIdx.x * 64 + pl;
    const int b = blockIdx.y, mod = blockIdx.z;
    const float* wgt = mod ? wgtD : wgtR;
    const int modb = mod * 2 + b;
    size_t base = (size_t)(modb * 4) * 128 * NPOS;
    const float* f = feat + base + pos;

    float s[3][4];
#pragma unroll
    for (int k = 0; k < 3; k++)
#pragma unroll
        for (int p = 0; p < 4; p++) s[k][p] = 0.f;

#pragma unroll 4
    for (int j = 0; j < 32; j++) {
        int c = cs * 32 + j;
        float w0 = __ldg(wgt + c), w1 = __ldg(wgt + 128 + c), w2 = __ldg(wgt + 256 + c);
#pragma unroll
        for (int p = 0; p < 4; p++) {
            float fv = f[(size_t)(p * 128 + c) * NPOS];
            s[0][p] = fmaf(w0, fv, s[0][p]);
            s[1][p] = fmaf(w1, fv, s[1][p]);
            s[2][p] = fmaf(w2, fv, s[2][p]);
        }
    }

    __shared__ float red[4][12][64];
#pragma unroll
    for (int k = 0; k < 3; k++)
#pragma unroll
        for (int p = 0; p < 4; p++)
            red[cs][k * 4 + p][pl] = s[k][p];
    __syncthreads();

    if (threadIdx.x < 64) {
        float ss[12];
#pragma unroll
        for (int j = 0; j < 12; j++)
            ss[j] = red[0][j][pl] + red[1][j][pl] + red[2][j][pl] + red[3][j][pl];

        const int OI[4][3] = {{1,2,3},{0,2,3},{0,1,3},{0,1,2}};
#pragma unroll
        for (int i = 0; i < 4; i++)
#pragma unroll
            for (int k = 0; k < 3; k++) {
                float sg = sigm(ss[k * 4 + i] - ss[k * 4 + OI[i][k]]);
                g_gate[(size_t)(modb * 12 + i * 3 + k) * NPOS + pos] = sg;
            }
    }
}

// ---------------------------------------------------------------------------
// g1b: messages. thread per (c, pos). grid: (1152, 2, 2), block 256.
// ---------------------------------------------------------------------------
__global__ __launch_bounds__(256)
void g1b_kernel(const float* __restrict__ dout, int it)
{
    const float* feat = it ? g_feat2 : dout;
    const int c   = blockIdx.x / 9;
    const int pos = (blockIdx.x % 9) * 256 + threadIdx.x;
    const int b = blockIdx.y, mod = blockIdx.z;
    const int modb = mod * 2 + b;
    size_t base = (size_t)(modb * 4) * 128 * NPOS;
    const float* f = feat + base + (size_t)c * NPOS + pos;

    float fv[4];
#pragma unroll
    for (int p = 0; p < 4; p++) fv[p] = f[(size_t)(p * 128) * NPOS];

    float sg[12];
#pragma unroll
    for (int g = 0; g < 12; g++)
        sg[g] = g_gate[(size_t)(modb * 12 + g) * NPOS + pos];

    const int OI[4][3] = {{1,2,3},{0,2,3},{0,1,3},{0,1,2}};
    const int c3 = c % 3;
    float* mo = g_m + base + (size_t)c * NPOS + pos;
#pragma unroll
    for (int i = 0; i < 4; i++) {
        float msum = 0.f;
#pragma unroll
        for (int k = 0; k < 3; k++) {
            int gi = 2 * k + c3;
            if (gi >= 3) gi -= 3;
            if (gi >= 3) gi -= 3;
            msum = fmaf(fv[OI[i][k]], sg[i * 3 + gi], msum);
        }
        mo[(size_t)(i * 128) * NPOS] = msum;
    }
}

// ---------------------------------------------------------------------------
// g2 via mma.sync tf32: z,r = sigmoid(W01 @ [m;feat] + b01)
// grid: (24 colblk, 2 oblk, 16 modbn), 256 thr, CTA 128o x 96col, K=256.
// ---------------------------------------------------------------------------
__global__ __launch_bounds__(256)
void g2_mma_kernel(const float* __restrict__ dout, int it,
                   const float* __restrict__ gbR, const float* __restrict__ gbD)
{
    extern __shared__ float smem[];
    float* As[2] = { smem,           smem + A_BUF };
    float* Bs[2] = { smem + 2*A_BUF, smem + 2*A_BUF + B_BUF };

    const float* feat = it ? g_feat2 : dout;
    const int tid = threadIdx.x;
    const int lane = tid & 31;
    const int wid = tid >> 5;
    const int wm = wid & 3;
    const int wn = wid >> 2;

    const int zid = blockIdx.z;
    const int mod = zid >> 3, bn = zid & 7;
    const int oblk = blockIdx.y;
    const int col0 = blockIdx.x * 96;

    const float* Agw  = g_gw + (size_t)mod * 3 * 128 * 256 + (size_t)oblk * 128 * 256;
    const float* bias = (mod ? gbD : gbR) + oblk * 128;
    size_t base = (size_t)(mod * 8 + bn) * 128 * NPOS;
    const float* F = feat + base;
    const float* M = g_m + base;

    const int arow = tid >> 1;
    const int ahalf = (tid & 1) * 16;
    const int tx  = tid & 31;
    const int grp = tid >> 5;

    float acc[2][6][4];
#pragma unroll
    for (int i = 0; i < 2; i++)
#pragma unroll
        for (int j = 0; j < 6; j++)
#pragma unroll
            for (int k = 0; k < 4; k++) acc[i][j][k] = 0.f;

#define GSTAGE(S, BUF) do {                                                   \
    int cc_ = (S) * 32;                                                       \
    const float* wrow_ = Agw + (size_t)arow * 256 + cc_ + ahalf;              \
    float* A_ = As[BUF]; float* B_ = Bs[BUF];                                 \
    _Pragma("unroll")                                                         \
    for (int j = 0; j < 4; j++) {                                             \
        float4 v = *(const float4*)(wrow_ + j * 4);                           \
        *(float4*)(A_ + arow * APITCH + ahalf + j * 4) = v;                   \
    }                                                                         \
    _Pragma("unroll")                                                         \
    for (int pb = 0; pb < 3; pb++) {                                          \
        int col = tx + 32 * pb;                                               \
        _Pragma("unroll")                                                     \
        for (int cb = 0; cb < 4; cb++) {                                      \
            int kk = grp + 8 * cb;                                            \
            int x = cc_ + kk;                                                 \
            float v = (x < 128) ? M[(size_t)x * NPOS + col0 + col]            \
                                : F[(size_t)(x - 128) * NPOS + col0 + col];   \
            B_[kk * BPITCH + col] = __uint_as_float(tf32r(v));                \
        }                                                                     \
    }                                                                         \
} while (0)

    GSTAGE(0, 0);
    __syncthreads();

    const int m0 = wm * 32;
    const int n0 = wn * 48;
    const int arow0 = lane >> 2;
    const int acol0 = lane & 3;
    const int brow0 = lane & 3;
    const int bcol0 = lane >> 2;

    for (int s = 0; s < 8; s++) {
        int buf = s & 1;
        if (s + 1 < 8) GSTAGE(s + 1, buf ^ 1);

        const float* A_ = As[buf];
        const float* B_ = Bs[buf];
#pragma unroll
        for (int k0 = 0; k0 < 32; k0 += 8) {
            uint32_t afr[2][4];
#pragma unroll
            for (int mt = 0; mt < 2; mt++) {
                int r = m0 + mt * 16 + arow0;
                afr[mt][0] = __float_as_uint(A_[r * APITCH + k0 + acol0]);
                afr[mt][1] = __float_as_uint(A_[(r + 8) * APITCH + k0 + acol0]);
                afr[mt][2] = __float_as_uint(A_[r * APITCH + k0 + acol0 + 4]);
                afr[mt][3] = __float_as_uint(A_[(r + 8) * APITCH + k0 + acol0 + 4]);
            }
#pragma unroll
            for (int nt = 0; nt < 6; nt++) {
                uint32_t bfr[2];
                int ncol = n0 + nt * 8 + bcol0;
                bfr[0] = __float_as_uint(B_[(k0 + brow0) * BPITCH + ncol]);
                bfr[1] = __float_as_uint(B_[(k0 + brow0 + 4) * BPITCH + ncol]);
                mma_tf32(acc[0][nt], afr[0], bfr);
                mma_tf32(acc[1][nt], afr[1], bfr);
            }
        }
        __syncthreads();
    }

    float* ob = (oblk == 0) ? (g_z + base) : (g_r + base);
#pragma unroll
    for (int mt = 0; mt < 2; mt++) {
#pragma unroll
        for (int half = 0; half < 2; half++) {
            int o = m0 + mt * 16 + half * 8 + (lane >> 2);
            float bv = __ldg(bias + o);
            float* orow = ob + (size_t)o * NPOS + col0;
#pragma unroll
            for (int nt = 0; nt < 6; nt++) {
                int col = n0 + nt * 8 + (lane & 3) * 2;
                orow[col]     = sigm(acc[mt][nt][half * 2 + 0] + bv);
                orow[col + 1] = sigm(acc[mt][nt][half * 2 + 1] + bv);
            }
        }
    }
#undef GSTAGE
}

// ---------------------------------------------------------------------------
// g3 via mma.sync tf32: cand = tanh(W2 @ [m; feat*r] + b2), fused GRU update
// grid: (24 colblk, 1, 16 modbn), 256 thr, CTA 128o x 96col, K=256.
// ---------------------------------------------------------------------------
__global__ __launch_bounds__(256)
void g3_mma_kernel(float* __restrict__ dout, int it,
                   const float* __restrict__ gbR, const float* __restrict__ gbD,
                   const float* __restrict__ gamR, const float* __restrict__ gamD)
{
    extern __shared__ float smem[];
    float* As[2] = { smem,           smem + A_BUF };
    float* Bs[2] = { smem + 2*A_BUF, smem + 2*A_BUF + B_BUF };

    const float* feat = it ? g_feat2 : dout;
    float* dst        = it ? dout : g_feat2;
    const int tid = threadIdx.x;
    const int lane = tid & 31;
    const int wid = tid >> 5;
    const int wm = wid & 3;
    const int wn = wid >> 2;

    const int zid = blockIdx.z;
    const int mod = zid >> 3, bn = zid & 7;
    const int col0 = blockIdx.x * 96;

    const float* Agw  = g_gw + (size_t)mod * 3 * 128 * 256 + (size_t)2 * 128 * 256;
    const float* bias = (mod ? gbD : gbR) + 2 * 128;
    float gam = mod ? __ldg(gamD) : __ldg(gamR);
    size_t base = (size_t)(mod * 8 + bn) * 128 * NPOS;
    const float* F = feat + base;
    const float* M = g_m + base;
    const float* R = g_r + base;

    const int arow = tid >> 1;
    const int ahalf = (tid & 1) * 16;
    const int tx  = tid & 31;
    const int grp = tid >> 5;

    float acc[2][6][4];
#pragma unroll
    for (int i = 0; i < 2; i++)
#pragma unroll
        for (int j = 0; j < 6; j++)
#pragma unroll
            for (int k = 0; k < 4; k++) acc[i][j][k] = 0.f;

#define G3STAGE(S, BUF) do {                                                  \
    int cc_ = (S) * 32;                                                       \
    const float* wrow_ = Agw + (size_t)arow * 256 + cc_ + ahalf;              \
    float* A_ = As[BUF]; float* B_ = Bs[BUF];                                 \
    _Pragma("unroll")                                                         \
    for (int j = 0; j < 4; j++) {                                             \
        float4 v = *(const float4*)(wrow_ + j * 4);                           \
        *(float4*)(A_ + arow * APITCH + ahalf + j * 4) = v;                   \
    }                                                                         \
    _Pragma("unroll")                                                         \
    for (int pb = 0; pb < 3; pb++) {                                          \
        int col = tx + 32 * pb;                                               \
        _Pragma("unroll")                                                     \
        for (int cb = 0; cb < 4; cb++) {                                      \
            int kk = grp + 8 * cb;                                            \
            int x = cc_ + kk;                                                 \
            float v;                                                          \
            if (x < 128) v = M[(size_t)x * NPOS + col0 + col];                \
            else {                                                            \
                size_t idx_ = (size_t)(x - 128) * NPOS + col0 + col;          \
                v = F[idx_] * R[idx_];                                        \
            }                                                                 \
            B_[kk * BPITCH + col] = __uint_as_float(tf32r(v));                \
        }                                                                     \
    }                                                                         \
} while (0)

    G3STAGE(0, 0);
    __syncthreads();

    const int m0 = wm * 32;
    const int n0 = wn * 48;
    const int arow0 = lane >> 2;
    const int acol0 = lane & 3;
    const int brow0 = lane & 3;
    const int bcol0 = lane >> 2;

    for (int s = 0; s < 8; s++) {
        int buf = s & 1;
        if (s + 1 < 8) G3STAGE(s + 1, buf ^ 1);

        const float* A_ = As[buf];
        const float* B_ = Bs[buf];
#pragma unroll
        for (int k0 = 0; k0 < 32; k0 += 8) {
            uint32_t afr[2][4];
#pragma unroll
            for (int mt = 0; mt < 2; mt++) {
                int r = m0 + mt * 16 + arow0;
                afr[mt][0] = __float_as_uint(A_[r * APITCH + k0 + acol0]);
                afr[mt][1] = __float_as_uint(A_[(r + 8) * APITCH + k0 + acol0]);
                afr[mt][2] = __float_as_uint(A_[r * APITCH + k0 + acol0 + 4]);
                afr[mt][3] = __float_as_uint(A_[(r + 8) * APITCH + k0 + acol0 + 4]);
            }
#pragma unroll
            for (int nt = 0; nt < 6; nt++) {
                uint32_t bfr[2];
                int ncol = n0 + nt * 8 + bcol0;
                bfr[0] = __float_as_uint(B_[(k0 + brow0) * BPITCH + ncol]);
                bfr[1] = __float_as_uint(B_[(k0 + brow0 + 4) * BPITCH + ncol]);
                mma_tf32(acc[0][nt], afr[0], bfr);
                mma_tf32(acc[1][nt], afr[1], bfr);
            }
        }
        __syncthreads();
    }

#pragma unroll
    for (int mt = 0; mt < 2; mt++) {
#pragma unroll
        for (int half = 0; half < 2; half++) {
            int o = m0 + mt * 16 + half * 8 + (lane >> 2);
            float bv = __ldg(bias + o);
#pragma unroll
            for (int nt = 0; nt < 6; nt++) {
                int col = col0 + n0 + nt * 8 + (lane & 3) * 2;
#pragma unroll
                for (int u = 0; u < 2; u++) {
                    size_t idx = base + (size_t)o * NPOS + col + u;
                    float cand = tanhf(acc[mt][nt][half * 2 + u] + bv);
                    float z = g_z[idx];
                    float f = feat[idx];
                    dst[idx] = fmaf(gam, fmaf(f, 1.f - z, cand * z), f);
                }
            }
        }
    }
#undef G3STAGE
}

// ---------------------------------------------------------------------------
extern "C" void kernel_launch(void* const* d_in, const int* in_sizes, int n_in,
                              void* d_out, int out_size)
{
    const float* feat_rgb = (const float*)d_in[0];
    const float* feat_dep = (const float*)d_in[1];
    const float* ppm_w_r  = (const float*)d_in[2];
    const float* ppm_s_r  = (const float*)d_in[3];
    const float* ppm_b_r  = (const float*)d_in[4];
    const float* ppm_w_d  = (const float*)d_in[5];
    const float* ppm_s_d  = (const float*)d_in[6];
    const float* ppm_b_d  = (const float*)d_in[7];
    const float* pa_w     = (const float*)d_in[8];
    const float* wgt_r    = (const float*)d_in[9];
    const float* gruw_r   = (const float*)d_in[10];
    const float* grub_r   = (const float*)d_in[11];
    const float* gam_r    = (const float*)d_in[12];
    const float* wgt_d    = (const float*)d_in[13];
    const float* gruw_d   = (const float*)d_in[14];
    const float* grub_d   = (const float*)d_in[15];
    const float* gam_d    = (const float*)d_in[16];
    float* out = (float*)d_out;

    cudaFuncSetAttribute(conv_mma_kernel,
                         cudaFuncAttributeMaxDynamicSharedMemorySize, CONV_SMEM);
    cudaFuncSetAttribute(g2_mma_kernel,
                         cudaFuncAttributeMaxDynamicSharedMemorySize, CONV_SMEM);
    cudaFuncSetAttribute(g3_mma_kernel,
                         cudaFuncAttributeMaxDynamicSharedMemorySize, CONV_SMEM);

    wt_prep_kernel<<<(2*4*9*128*512 + 255) / 256, 256>>>(ppm_w_r, ppm_w_d);
    gw_prep_kernel<<<(2*3*128*256 + 255) / 256, 256>>>(gruw_r, gruw_d);
    conv_mma_kernel<<<dim3(48, 8), 256, CONV_SMEM>>>(feat_rgb, feat_dep,
                                                     ppm_s_r, ppm_b_r,
                                                     ppm_s_d, ppm_b_d, out);
    pa_kernel<<<72, 256>>>(out, pa_w);
    for (int it = 0; it < 2; it++) {
        g1a_kernel<<<dim3(36, 2, 2), 256>>>(out, it, wgt_r, wgt_d);
        g1b_kernel<<<dim3(1152, 2, 2), 256>>>(out, it);
        g2_mma_kernel<<<dim3(24, 2, 16), 256, CONV_SMEM>>>(out, it, grub_r, grub_d);
        g3_mma_kernel<<<dim3(24, 1, 16), 256, CONV_SMEM>>>(out, it, grub_r, grub_d,
                                                           gam_r, gam_d);
    }
}

// round 8
// speedup vs baseline: 4.8470x; 1.4400x over previous
#include <cuda_runtime.h>
#include <cuda_fp16.h>
#include <math.h>
#include <stdint.h>

#define NPOS 2304
#define FEATSZ (2*2*4*128*NPOS)

// Scratch
__device__ float  g_feat2[FEATSZ];
__device__ float  g_m[FEATSZ];
__device__ float  g_z[FEATSZ];
__device__ float  g_r[FEATSZ];
__device__ __half g_wth[2*4*9*128*512]; // conv weights [mn][tap][co][ci], fp16
__device__ float  g_gw[2*3*128*256];    // gru weights [mod][gate][o][k], tf32-rounded
__device__ float  g_gate[2*2*12*NPOS];  // edge gates  [modb][i*3+k][pos]

__device__ __forceinline__ float sigm(float x) { return 1.f / (1.f + expf(-x)); }

__device__ __forceinline__ uint32_t tf32r(float v) {
    uint32_t o;
    asm("cvt.rna.tf32.f32 %0, %1;" : "=r"(o) : "f"(v));
    return o;
}

__device__ __forceinline__ void mma_tf32(float* c, const uint32_t* a, const uint32_t* b) {
    asm volatile(
        "mma.sync.aligned.m16n8k8.row.col.f32.tf32.tf32.f32 "
        "{%0,%1,%2,%3}, {%4,%5,%6,%7}, {%8,%9}, {%0,%1,%2,%3};"
        : "+f"(c[0]), "+f"(c[1]), "+f"(c[2]), "+f"(c[3])
        : "r"(a[0]), "r"(a[1]), "r"(a[2]), "r"(a[3]), "r"(b[0]), "r"(b[1]));
}

__device__ __forceinline__ void mma_f16(float* c, const uint32_t* a, const uint32_t* b) {
    asm volatile(
        "mma.sync.aligned.m16n8k16.row.col.f32.f16.f16.f32 "
        "{%0,%1,%2,%3}, {%4,%5,%6,%7}, {%8,%9}, {%0,%1,%2,%3};"
        : "+f"(c[0]), "+f"(c[1]), "+f"(c[2]), "+f"(c[3])
        : "r"(a[0]), "r"(a[1]), "r"(a[2]), "r"(a[3]), "r"(b[0]), "r"(b[1]));
}

// ---------------------------------------------------------------------------
// Prep kernels
// ---------------------------------------------------------------------------
__global__ void wt_prep_kernel(const float* __restrict__ wR, const float* __restrict__ wD)
{
    int e = blockIdx.x * 256 + threadIdx.x;
    if (e >= 2*4*9*128*512) return;
    int ci = e & 511;
    int r = e >> 9;
    int co = r & 127; r >>= 7;
    int tap = r % 9; r /= 9;
    int node = r & 3;
    int mod = r >> 2;
    const float* w = mod ? wD : wR;
    g_wth[e] = __float2half_rn(w[((size_t)(node*128 + co)*512 + ci)*9 + tap]);
}

__global__ void gw_prep_kernel(const float* __restrict__ gwR, const float* __restrict__ gwD)
{
    int e = blockIdx.x * 256 + threadIdx.x;
    if (e >= 2*3*128*256) return;
    int mod = e / (3*128*256);
    int x   = e % (3*128*256);
    const float* w = mod ? gwD : gwR;
    g_gw[e] = __uint_as_float(tf32r(w[x]));
}

// ---------------------------------------------------------------------------
// Conv via mma.sync fp16 m16n8k16 implicit GEMM.
// grid: (48 = b*24 + rowpair, 8 = mod*4+node), 256 threads (8 warps: 4m x 2n)
// CTA tile: 128 co x 96 pos, K = 144 stages of 32. Static smem, 2 CTA/SM.
// ---------------------------------------------------------------------------
#define PA_H 40
#define PB_H 40
#define A_BUF_H (128*PA_H)
#define B_BUF_H (96*PB_H)

__global__ __launch_bounds__(256)
void conv_mma_kernel(const float* __restrict__ inR, const float* __restrict__ inD,
                     const float* __restrict__ sR, const float* __restrict__ bR,
                     const float* __restrict__ sD, const float* __restrict__ bD,
                     float* __restrict__ out)
{
    __shared__ __half smA[2][A_BUF_H];
    __shared__ __half smB[2][B_BUF_H];

    const int tid = threadIdx.x;
    const int lane = tid & 31;
    const int wid = tid >> 5;
    const int wm = wid & 3;
    const int wn = wid >> 2;

    const int mn   = blockIdx.y;
    const int mod  = mn >> 2, node = mn & 3;
    const int dil  = 1 << node;
    const int b    = blockIdx.x / 24;
    const int y0   = (blockIdx.x % 24) * 2;

    const float* __restrict__ in = (mod ? inD : inR) + (size_t)b * 512 * NPOS;
    const __half* __restrict__ Wt = g_wth + (size_t)mn * 9 * 128 * 512;

    const int arow = tid >> 1;             // A staging row 0..127
    const int ahb  = (tid & 1) * 16;       // A staging half-block

    float acc[2][6][4];
#pragma unroll
    for (int i = 0; i < 2; i++)
#pragma unroll
        for (int j = 0; j < 6; j++)
#pragma unroll
            for (int k = 0; k < 4; k++) acc[i][j][k] = 0.f;

#define STAGE(S, BUF) do {                                                    \
    int tap_ = (S) >> 4;                                                      \
    int cc_  = ((S) & 15) * 32;                                               \
    int dy_  = (tap_ / 3 - 1) * dil;                                          \
    int dx_  = (tap_ % 3 - 1) * dil;                                          \
    { const __half* wsrc = Wt + ((size_t)(tap_ * 128) + arow) * 512 + cc_ + ahb; \
      uint4 v0 = *(const uint4*)(wsrc);                                       \
      uint4 v1 = *(const uint4*)(wsrc + 8);                                   \
      __half* ad = &smA[BUF][arow * PA_H + ahb];                              \
      *(uint4*)(ad) = v0; *(uint4*)(ad + 8) = v1; }                           \
    _Pragma("unroll")                                                         \
    for (int pb = 0; pb < 3; pb++) {                                          \
        int posl = lane + 32 * pb;                                            \
        int ry = posl / 48;                                                   \
        int x  = posl - ry * 48;                                              \
        int xs = x + dx_, ys = y0 + ry + dy_;                                 \
        bool ok = ((unsigned)xs < 48u) && ((unsigned)ys < 48u);               \
        int goff = ys * 48 + xs;                                              \
        _Pragma("unroll")                                                     \
        for (int pp = 0; pp < 2; pp++) {                                      \
            int ci = 2 * (wid + 8 * pp);                                      \
            float v0 = 0.f, v1 = 0.f;                                         \
            if (ok) {                                                         \
                v0 = in[(size_t)(cc_ + ci) * NPOS + goff];                    \
                v1 = in[(size_t)(cc_ + ci + 1) * NPOS + goff];                \
            }                                                                 \
            *(half2*)&smB[BUF][posl * PB_H + ci] = __floats2half2_rn(v0, v1); \
        }                                                                     \
    }                                                                         \
} while (0)

    STAGE(0, 0);
    __syncthreads();

    const int m0 = wm * 32;
    const int n0 = wn * 48;
    const int arow0 = lane >> 2;
    const int acol0 = lane & 3;
    const int brow0 = lane & 3;
    const int bcol0 = lane >> 2;

    for (int s = 0; s < 144; s++) {
        int buf = s & 1;
        if (s + 1 < 144) STAGE(s + 1, buf ^ 1);

        const __half* A_ = smA[buf];
        const __half* B_ = smB[buf];
#pragma unroll
        for (int k0 = 0; k0 < 32; k0 += 16) {
            uint32_t af[2][4];
#pragma unroll
            for (int mt = 0; mt < 2; mt++) {
                int r = m0 + mt * 16 + arow0;
                af[mt][0] = *(const uint32_t*)&A_[r * PA_H + k0 + 2 * acol0];
                af[mt][1] = *(const uint32_t*)&A_[(r + 8) * PA_H + k0 + 2 * acol0];
                af[mt][2] = *(const uint32_t*)&A_[r * PA_H + k0 + 2 * acol0 + 8];
                af[mt][3] = *(const uint32_t*)&A_[(r + 8) * PA_H + k0 + 2 * acol0 + 8];
            }
#pragma unroll
            for (int nt = 0; nt < 6; nt++) {
                int ncol = n0 + nt * 8 + bcol0;
                uint32_t bf[2];
                bf[0] = *(const uint32_t*)&B_[ncol * PB_H + k0 + 2 * brow0];
                bf[1] = *(const uint32_t*)&B_[ncol * PB_H + k0 + 2 * brow0 + 8];
                mma_f16(acc[0][nt], af[0], bf);
                mma_f16(acc[1][nt], af[1], bf);
            }
        }
        __syncthreads();
    }

    const float* sc = (mod ? sD : sR) + node * 128;
    const float* bi = (mod ? bD : bR) + node * 128;
    float* outp = out + ((size_t)((mod * 2 + b) * 4 + node) * 128) * NPOS + y0 * 48;

#pragma unroll
    for (int mt = 0; mt < 2; mt++) {
#pragma unroll
        for (int half = 0; half < 2; half++) {
            int co = m0 + mt * 16 + half * 8 + (lane >> 2);
            float s = __ldg(sc + co), bb = __ldg(bi + co);
            float* orow = outp + (size_t)co * NPOS;
#pragma unroll
            for (int nt = 0; nt < 6; nt++) {
                int pos = n0 + nt * 8 + (lane & 3) * 2;
                float v0 = fmaxf(fmaf(acc[mt][nt][half * 2 + 0], s, bb), 0.f);
                float v1 = fmaxf(fmaf(acc[mt][nt][half * 2 + 1], s, bb), 0.f);
                *(float2*)(orow + pos) = make_float2(v0, v1);
            }
        }
    }
#undef STAGE
}

// ---------------------------------------------------------------------------
// PA: register-resident cross-modal gating.
// block 256 = 64 columns x 4 channel-splits; grid 288 = 8 bn x 36 postiles.
// ---------------------------------------------------------------------------
__global__ __launch_bounds__(256)
void pa_kernel(float* __restrict__ feat, const float* __restrict__ paw)
{
    const int pl = threadIdx.x & 63;
    const int cs = threadIdx.x >> 6;
    const int bn  = blockIdx.x / 36;
    const int pos = (blockIdx.x % 36) * 64 + pl;
    float* pr = feat + (size_t)bn * 128 * NPOS + pos;
    float* pd = feat + (size_t)(8 + bn) * 128 * NPOS + pos;

    float r[32], d[32];
#pragma unroll 8
    for (int j = 0; j < 32; j++) {
        int c = cs * 32 + j;
        r[j] = pr[(size_t)c * NPOS];
        d[j] = pd[(size_t)c * NPOS];
    }

    __shared__ float red[2][4][2][64];

#pragma unroll
    for (int it = 0; it < 2; it++) {
        float s0 = 0.f, s1 = 0.f;
#pragma unroll 8
        for (int j = 0; j < 32; j++) {
            int c = cs * 32 + j;
            float df = r[j] - d[j];
            s0 = fmaf(df,  __ldg(paw + c),       s0);
            s1 = fmaf(-df, __ldg(paw + 128 + c), s1);
        }
        red[it][cs][0][pl] = s0;
        red[it][cs][1][pl] = s1;
        __syncthreads();
        float S0 = red[it][0][0][pl] + red[it][1][0][pl] + red[it][2][0][pl] + red[it][3][0][pl];
        float S1 = red[it][0][1][pl] + red[it][1][1][pl] + red[it][2][1][pl] + red[it][3][1][pl];
        float g0 = sigm(S0), g1 = sigm(S1);
#pragma unroll 8
        for (int j = 0; j < 32; j++) {
            float t = r[j];
            r[j] = fmaf(d[j], g1, t);
            d[j] = fmaf(t, g0, d[j]);
        }
    }

#pragma unroll 8
    for (int j = 0; j < 32; j++) {
        int c = cs * 32 + j;
        pr[(size_t)c * NPOS] = r[j];
        pd[(size_t)c * NPOS] = d[j];
    }
}

// ---------------------------------------------------------------------------
// g1a: edge gates. block 256 = 64 pos x 4 channel-splits; smem reduction.
// ---------------------------------------------------------------------------
__global__ __launch_bounds__(256)
void g1a_kernel(const float* __restrict__ dout, int it,
                const float* __restrict__ wgtR, const float* __restrict__ wgtD)
{
    const float* feat = it ? g_feat2 : dout;
    const int pl = threadIdx.x & 63;
    const int cs = threadIdx.x >> 6;
    const int pos = blockIdx.x * 64 + pl;
    const int b = blockIdx.y, mod = blockIdx.z;
    const float* wgt = mod ? wgtD : wgtR;
    const int modb = mod * 2 + b;
    size_t base = (size_t)(modb * 4) * 128 * NPOS;
    const float* f = feat + base + pos;

    float s[3][4];
#pragma unroll
    for (int k = 0; k < 3; k++)
#pragma unroll
        for (int p = 0; p < 4; p++) s[k][p] = 0.f;

#pragma unroll 4
    for (int j = 0; j < 32; j++) {
        int c = cs * 32 + j;
        float w0 = __ldg(wgt + c), w1 = __ldg(wgt + 128 + c), w2 = __ldg(wgt + 256 + c);
#pragma unroll
        for (int p = 0; p < 4; p++) {
            float fv = f[(size_t)(p * 128 + c) * NPOS];
            s[0][p] = fmaf(w0, fv, s[0][p]);
            s[1][p] = fmaf(w1, fv, s[1][p]);
            s[2][p] = fmaf(w2, fv, s[2][p]);
        }
    }

    __shared__ float red[4][12][64];
#pragma unroll
    for (int k = 0; k < 3; k++)
#pragma unroll
        for (int p = 0; p < 4; p++)
            red[cs][k * 4 + p][pl] = s[k][p];
    __syncthreads();

    if (threadIdx.x < 64) {
        float ss[12];
#pragma unroll
        for (int j = 0; j < 12; j++)
            ss[j] = red[0][j][pl] + red[1][j][pl] + red[2][j][pl] + red[3][j][pl];

        const int OI[4][3] = {{1,2,3},{0,2,3},{0,1,3},{0,1,2}};
#pragma unroll
        for (int i = 0; i < 4; i++)
#pragma unroll
            for (int k = 0; k < 3; k++) {
                float sg = sigm(ss[k * 4 + i] - ss[k * 4 + OI[i][k]]);
                g_gate[(size_t)(modb * 12 + i * 3 + k) * NPOS + pos] = sg;
            }
    }
}

// ---------------------------------------------------------------------------
// g1b: messages. thread per (c, pos).
// ---------------------------------------------------------------------------
__global__ __launch_bounds__(256)
void g1b_kernel(const float* __restrict__ dout, int it)
{
    const float* feat = it ? g_feat2 : dout;
    const int c   = blockIdx.x / 9;
    const int pos = (blockIdx.x % 9) * 256 + threadIdx.x;
    const int b = blockIdx.y, mod = blockIdx.z;
    const int modb = mod * 2 + b;
    size_t base = (size_t)(modb * 4) * 128 * NPOS;
    const float* f = feat + base + (size_t)c * NPOS + pos;

    float fv[4];
#pragma unroll
    for (int p = 0; p < 4; p++) fv[p] = f[(size_t)(p * 128) * NPOS];

    float sg[12];
#pragma unroll
    for (int g = 0; g < 12; g++)
        sg[g] = g_gate[(size_t)(modb * 12 + g) * NPOS + pos];

    const int OI[4][3] = {{1,2,3},{0,2,3},{0,1,3},{0,1,2}};
    const int c3 = c % 3;
    float* mo = g_m + base + (size_t)c * NPOS + pos;
#pragma unroll
    for (int i = 0; i < 4; i++) {
        float msum = 0.f;
#pragma unroll
        for (int k = 0; k < 3; k++) {
            int gi = 2 * k + c3;
            if (gi >= 3) gi -= 3;
            if (gi >= 3) gi -= 3;
            msum = fmaf(fv[OI[i][k]], sg[i * 3 + gi], msum);
        }
        mo[(size_t)(i * 128) * NPOS] = msum;
    }
}

// ---------------------------------------------------------------------------
// g2 via mma.sync tf32 (unchanged, proven)
// ---------------------------------------------------------------------------
#define APITCH 36
#define BPITCH 104
#define A_BUF (128*APITCH)
#define B_BUF (32*BPITCH)
#define GRU_SMEM ((2*A_BUF + 2*B_BUF)*4)

__global__ __launch_bounds__(256)
void g2_mma_kernel(const float* __restrict__ dout, int it,
                   const float* __restrict__ gbR, const float* __restrict__ gbD)
{
    extern __shared__ float smem[];
    float* As[2] = { smem,           smem + A_BUF };
    float* Bs[2] = { smem + 2*A_BUF, smem + 2*A_BUF + B_BUF };

    const float* feat = it ? g_feat2 : dout;
    const int tid = threadIdx.x;
    const int lane = tid & 31;
    const int wid = tid >> 5;
    const int wm = wid & 3;
    const int wn = wid >> 2;

    const int zid = blockIdx.z;
    const int mod = zid >> 3, bn = zid & 7;
    const int oblk = blockIdx.y;
    const int col0 = blockIdx.x * 96;

    const float* Agw  = g_gw + (size_t)mod * 3 * 128 * 256 + (size_t)oblk * 128 * 256;
    const float* bias = (mod ? gbD : gbR) + oblk * 128;
    size_t base = (size_t)(mod * 8 + bn) * 128 * NPOS;
    const float* F = feat + base;
    const float* M = g_m + base;

    const int arow = tid >> 1;
    const int ahalf = (tid & 1) * 16;
    const int tx  = tid & 31;
    const int grp = tid >> 5;

    float acc[2][6][4];
#pragma unroll
    for (int i = 0; i < 2; i++)
#pragma unroll
        for (int j = 0; j < 6; j++)
#pragma unroll
            for (int k = 0; k < 4; k++) acc[i][j][k] = 0.f;

#define GSTAGE(S, BUF) do {                                                   \
    int cc_ = (S) * 32;                                                       \
    const float* wrow_ = Agw + (size_t)arow * 256 + cc_ + ahalf;              \
    float* A_ = As[BUF]; float* B_ = Bs[BUF];                                 \
    _Pragma("unroll")                                                         \
    for (int j = 0; j < 4; j++) {                                             \
        float4 v = *(const float4*)(wrow_ + j * 4);                           \
        *(float4*)(A_ + arow * APITCH + ahalf + j * 4) = v;                   \
    }                                                                         \
    _Pragma("unroll")                                                         \
    for (int pb = 0; pb < 3; pb++) {                                          \
        int col = tx + 32 * pb;                                               \
        _Pragma("unroll")                                                     \
        for (int cb = 0; cb < 4; cb++) {                                      \
            int kk = grp + 8 * cb;                                            \
            int x = cc_ + kk;                                                 \
            float v = (x < 128) ? M[(size_t)x * NPOS + col0 + col]            \
                                : F[(size_t)(x - 128) * NPOS + col0 + col];   \
            B_[kk * BPITCH + col] = __uint_as_float(tf32r(v));                \
        }                                                                     \
    }                                                                         \
} while (0)

    GSTAGE(0, 0);
    __syncthreads();

    const int m0 = wm * 32;
    const int n0 = wn * 48;
    const int arow0 = lane >> 2;
    const int acol0 = lane & 3;
    const int brow0 = lane & 3;
    const int bcol0 = lane >> 2;

    for (int s = 0; s < 8; s++) {
        int buf = s & 1;
        if (s + 1 < 8) GSTAGE(s + 1, buf ^ 1);

        const float* A_ = As[buf];
        const float* B_ = Bs[buf];
#pragma unroll
        for (int k0 = 0; k0 < 32; k0 += 8) {
            uint32_t afr[2][4];
#pragma unroll
            for (int mt = 0; mt < 2; mt++) {
                int r = m0 + mt * 16 + arow0;
                afr[mt][0] = __float_as_uint(A_[r * APITCH + k0 + acol0]);
                afr[mt][1] = __float_as_uint(A_[(r + 8) * APITCH + k0 + acol0]);
                afr[mt][2] = __float_as_uint(A_[r * APITCH + k0 + acol0 + 4]);
                afr[mt][3] = __float_as_uint(A_[(r + 8) * APITCH + k0 + acol0 + 4]);
            }
#pragma unroll
            for (int nt = 0; nt < 6; nt++) {
                uint32_t bfr[2];
                int ncol = n0 + nt * 8 + bcol0;
                bfr[0] = __float_as_uint(B_[(k0 + brow0) * BPITCH + ncol]);
                bfr[1] = __float_as_uint(B_[(k0 + brow0 + 4) * BPITCH + ncol]);
                mma_tf32(acc[0][nt], afr[0], bfr);
                mma_tf32(acc[1][nt], afr[1], bfr);
            }
        }
        __syncthreads();
    }

    float* ob = (oblk == 0) ? (g_z + base) : (g_r + base);
#pragma unroll
    for (int mt = 0; mt < 2; mt++) {
#pragma unroll
        for (int half = 0; half < 2; half++) {
            int o = m0 + mt * 16 + half * 8 + (lane >> 2);
            float bv = __ldg(bias + o);
            float* orow = ob + (size_t)o * NPOS + col0;
#pragma unroll
            for (int nt = 0; nt < 6; nt++) {
                int col = n0 + nt * 8 + (lane & 3) * 2;
                orow[col]     = sigm(acc[mt][nt][half * 2 + 0] + bv);
                orow[col + 1] = sigm(acc[mt][nt][half * 2 + 1] + bv);
            }
        }
    }
#undef GSTAGE
}

// ---------------------------------------------------------------------------
// g3 via mma.sync tf32 (unchanged, proven)
// ---------------------------------------------------------------------------
__global__ __launch_bounds__(256)
void g3_mma_kernel(float* __restrict__ dout, int it,
                   const float* __restrict__ gbR, const float* __restrict__ gbD,
                   const float* __restrict__ gamR, const float* __restrict__ gamD)
{
    extern __shared__ float smem[];
    float* As[2] = { smem,           smem + A_BUF };
    float* Bs[2] = { smem + 2*A_BUF, smem + 2*A_BUF + B_BUF };

    const float* feat = it ? g_feat2 : dout;
    float* dst        = it ? dout : g_feat2;
    const int tid = threadIdx.x;
    const int lane = tid & 31;
    const int wid = tid >> 5;
    const int wm = wid & 3;
    const int wn = wid >> 2;

    const int zid = blockIdx.z;
    const int mod = zid >> 3, bn = zid & 7;
    const int col0 = blockIdx.x * 96;

    const float* Agw  = g_gw + (size_t)mod * 3 * 128 * 256 + (size_t)2 * 128 * 256;
    const float* bias = (mod ? gbD : gbR) + 2 * 128;
    float gam = mod ? __ldg(gamD) : __ldg(gamR);
    size_t base = (size_t)(mod * 8 + bn) * 128 * NPOS;
    const float* F = feat + base;
    const float* M = g_m + base;
    const float* R = g_r + base;

    const int arow = tid >> 1;
    const int ahalf = (tid & 1) * 16;
    const int tx  = tid & 31;
    const int grp = tid >> 5;

    float acc[2][6][4];
#pragma unroll
    for (int i = 0; i < 2; i++)
#pragma unroll
        for (int j = 0; j < 6; j++)
#pragma unroll
            for (int k = 0; k < 4; k++) acc[i][j][k] = 0.f;

#define G3STAGE(S, BUF) do {                                                  \
    int cc_ = (S) * 32;                                                       \
    const float* wrow_ = Agw + (size_t)arow * 256 + cc_ + ahalf;              \
    float* A_ = As[BUF]; float* B_ = Bs[BUF];                                 \
    _Pragma("unroll")                                                         \
    for (int j = 0; j < 4; j++) {                                             \
        float4 v = *(const float4*)(wrow_ + j * 4);                           \
        *(float4*)(A_ + arow * APITCH + ahalf + j * 4) = v;                   \
    }                                                                         \
    _Pragma("unroll")                                                         \
    for (int pb = 0; pb < 3; pb++) {                                          \
        int col = tx + 32 * pb;                                               \
        _Pragma("unroll")                                                     \
        for (int cb = 0; cb < 4; cb++) {                                      \
            int kk = grp + 8 * cb;                                            \
            int x = cc_ + kk;                                                 \
            float v;                                                          \
            if (x < 128) v = M[(size_t)x * NPOS + col0 + col];                \
            else {                                                            \
                size_t idx_ = (size_t)(x - 128) * NPOS + col0 + col;          \
                v = F[idx_] * R[idx_];                                        \
            }                                                                 \
            B_[kk * BPITCH + col] = __uint_as_float(tf32r(v));                \
        }                                                                     \
    }                                                                         \
} while (0)

    G3STAGE(0, 0);
    __syncthreads();

    const int m0 = wm * 32;
    const int n0 = wn * 48;
    const int arow0 = lane >> 2;
    const int acol0 = lane & 3;
    const int brow0 = lane & 3;
    const int bcol0 = lane >> 2;

    for (int s = 0; s < 8; s++) {
        int buf = s & 1;
        if (s + 1 < 8) G3STAGE(s + 1, buf ^ 1);

        const float* A_ = As[buf];
        const float* B_ = Bs[buf];
#pragma unroll
        for (int k0 = 0; k0 < 32; k0 += 8) {
            uint32_t afr[2][4];
#pragma unroll
            for (int mt = 0; mt < 2; mt++) {
                int r = m0 + mt * 16 + arow0;
                afr[mt][0] = __float_as_uint(A_[r * APITCH + k0 + acol0]);
                afr[mt][1] = __float_as_uint(A_[(r + 8) * APITCH + k0 + acol0]);
                afr[mt][2] = __float_as_uint(A_[r * APITCH + k0 + acol0 + 4]);
                afr[mt][3] = __float_as_uint(A_[(r + 8) * APITCH + k0 + acol0 + 4]);
            }
#pragma unroll
            for (int nt = 0; nt < 6; nt++) {
                uint32_t bfr[2];
                int ncol = n0 + nt * 8 + bcol0;
                bfr[0] = __float_as_uint(B_[(k0 + brow0) * BPITCH + ncol]);
                bfr[1] = __float_as_uint(B_[(k0 + brow0 + 4) * BPITCH + ncol]);
                mma_tf32(acc[0][nt], afr[0], bfr);
                mma_tf32(acc[1][nt], afr[1], bfr);
            }
        }
        __syncthreads();
    }

#pragma unroll
    for (int mt = 0; mt < 2; mt++) {
#pragma unroll
        for (int half = 0; half < 2; half++) {
            int o = m0 + mt * 16 + half * 8 + (lane >> 2);
            float bv = __ldg(bias + o);
#pragma unroll
            for (int nt = 0; nt < 6; nt++) {
                int col = col0 + n0 + nt * 8 + (lane & 3) * 2;
#pragma unroll
                for (int u = 0; u < 2; u++) {
                    size_t idx = base + (size_t)o * NPOS + col + u;
                    float cand = tanhf(acc[mt][nt][half * 2 + u] + bv);
                    float z = g_z[idx];
                    float f = feat[idx];
                    dst[idx] = fmaf(gam, fmaf(f, 1.f - z, cand * z), f);
                }
            }
        }
    }
#undef G3STAGE
}

// ---------------------------------------------------------------------------
extern "C" void kernel_launch(void* const* d_in, const int* in_sizes, int n_in,
                              void* d_out, int out_size)
{
    const float* feat_rgb = (const float*)d_in[0];
    const float* feat_dep = (const float*)d_in[1];
    const float* ppm_w_r  = (const float*)d_in[2];
    const float* ppm_s_r  = (const float*)d_in[3];
    const float* ppm_b_r  = (const float*)d_in[4];
    const float* ppm_w_d  = (const float*)d_in[5];
    const float* ppm_s_d  = (const float*)d_in[6];
    const float* ppm_b_d  = (const float*)d_in[7];
    const float* pa_w     = (const float*)d_in[8];
    const float* wgt_r    = (const float*)d_in[9];
    const float* gruw_r   = (const float*)d_in[10];
    const float* grub_r   = (const float*)d_in[11];
    const float* gam_r    = (const float*)d_in[12];
    const float* wgt_d    = (const float*)d_in[13];
    const float* gruw_d   = (const float*)d_in[14];
    const float* grub_d   = (const float*)d_in[15];
    const float* gam_d    = (const float*)d_in[16];
    float* out = (float*)d_out;

    cudaFuncSetAttribute(g2_mma_kernel,
                         cudaFuncAttributeMaxDynamicSharedMemorySize, GRU_SMEM);
    cudaFuncSetAttribute(g3_mma_kernel,
                         cudaFuncAttributeMaxDynamicSharedMemorySize, GRU_SMEM);

    wt_prep_kernel<<<(2*4*9*128*512 + 255) / 256, 256>>>(ppm_w_r, ppm_w_d);
    gw_prep_kernel<<<(2*3*128*256 + 255) / 256, 256>>>(gruw_r, gruw_d);
    conv_mma_kernel<<<dim3(48, 8), 256>>>(feat_rgb, feat_dep,
                                          ppm_s_r, ppm_b_r,
                                          ppm_s_d, ppm_b_d, out);
    pa_kernel<<<288, 256>>>(out, pa_w);
    for (int it = 0; it < 2; it++) {
        g1a_kernel<<<dim3(36, 2, 2), 256>>>(out, it, wgt_r, wgt_d);
        g1b_kernel<<<dim3(1152, 2, 2), 256>>>(out, it);
        g2_mma_kernel<<<dim3(24, 2, 16), 256, GRU_SMEM>>>(out, it, grub_r, grub_d);
        g3_mma_kernel<<<dim3(24, 1, 16), 256, GRU_SMEM>>>(out, it, grub_r, grub_d,
                                                          gam_r, gam_d);
    }
}

// round 9
// speedup vs baseline: 5.7552x; 1.1874x over previous
#include <cuda_runtime.h>
#include <cuda_fp16.h>
#include <math.h>
#include <stdint.h>

#define NPOS 2304
#define FEATSZ (2*2*4*128*NPOS)

// Scratch
__device__ float  g_feat2[FEATSZ];
__device__ float  g_m[FEATSZ];
__device__ float  g_z[FEATSZ];
__device__ float  g_r[FEATSZ];
__device__ __half g_wth[2*4*9*128*512];  // conv weights [mn][tap][co][ci], fp16
__device__ __half g_gwh[2*3*128*256];    // gru weights  [mod][gate][o][k], fp16
__device__ __half g_inh[2*2*512*NPOS];   // conv input   [mb][cpair][pos][2], fp16
__device__ float  g_gate[2*2*12*NPOS];   // edge gates   [modb][i*3+k][pos]

__device__ __forceinline__ float sigm(float x) { return 1.f / (1.f + expf(-x)); }

__device__ __forceinline__ void mma_f16(float* c, const uint32_t* a, const uint32_t* b) {
    asm volatile(
        "mma.sync.aligned.m16n8k16.row.col.f32.f16.f16.f32 "
        "{%0,%1,%2,%3}, {%4,%5,%6,%7}, {%8,%9}, {%0,%1,%2,%3};"
        : "+f"(c[0]), "+f"(c[1]), "+f"(c[2]), "+f"(c[3])
        : "r"(a[0]), "r"(a[1]), "r"(a[2]), "r"(a[3]), "r"(b[0]), "r"(b[1]));
}

// ---------------------------------------------------------------------------
// Prep kernels
// ---------------------------------------------------------------------------
__global__ void wt_prep_kernel(const float* __restrict__ wR, const float* __restrict__ wD)
{
    int e = blockIdx.x * 256 + threadIdx.x;
    if (e >= 2*4*9*128*512) return;
    int ci = e & 511;
    int r = e >> 9;
    int co = r & 127; r >>= 7;
    int tap = r % 9; r /= 9;
    int node = r & 3;
    int mod = r >> 2;
    const float* w = mod ? wD : wR;
    g_wth[e] = __float2half_rn(w[((size_t)(node*128 + co)*512 + ci)*9 + tap]);
}

__global__ void gwh_prep_kernel(const float* __restrict__ gwR, const float* __restrict__ gwD)
{
    int e = blockIdx.x * 256 + threadIdx.x;
    if (e >= 2*3*128*256) return;
    int mod = e / (3*128*256);
    int x   = e % (3*128*256);
    const float* w = mod ? gwD : gwR;
    g_gwh[e] = __float2half_rn(w[x]);
}

// channel-pair interleave: g_inh[((mb*256 + cp)*NPOS + pos)*2 + {0,1}]
__global__ void in_prep_kernel(const float* __restrict__ inR, const float* __restrict__ inD)
{
    int e = blockIdx.x * 256 + threadIdx.x;
    if (e >= 4 * 256 * NPOS) return;
    int pos = e % NPOS;
    int r = e / NPOS;
    int cp = r & 255;
    int mb = r >> 8;                 // mod*2 + b
    const float* src = ((mb >> 1) ? inD : inR)
                     + ((size_t)(mb & 1) * 512 + 2 * cp) * NPOS + pos;
    *(half2*)&g_inh[((size_t)(mb * 256 + cp) * NPOS + pos) * 2] =
        __floats2half2_rn(src[0], src[NPOS]);
}

// ---------------------------------------------------------------------------
// Conv via mma.sync fp16 m16n8k16 implicit GEMM; fp16 pre-converted input.
// grid: (48 = b*24 + rowpair, 8 = mod*4+node), 256 threads (8 warps: 4m x 2n)
// ---------------------------------------------------------------------------
#define PA_H 40
#define PB_H 40
#define A_BUF_H (128*PA_H)
#define B_BUF_H (96*PB_H)

__global__ __launch_bounds__(256)
void conv_mma_kernel(const float* __restrict__ sR, const float* __restrict__ bR,
                     const float* __restrict__ sD, const float* __restrict__ bD,
                     float* __restrict__ out)
{
    __shared__ __half smA[2][A_BUF_H];
    __shared__ __half smB[2][B_BUF_H];

    const int tid = threadIdx.x;
    const int lane = tid & 31;
    const int wid = tid >> 5;
    const int wm = wid & 3;
    const int wn = wid >> 2;

    const int mn   = blockIdx.y;
    const int mod  = mn >> 2, node = mn & 3;
    const int dil  = 1 << node;
    const int b    = blockIdx.x / 24;
    const int y0   = (blockIdx.x % 24) * 2;

    const __half* __restrict__ inh = g_inh + (size_t)(mod * 2 + b) * 256 * NPOS * 2;
    const __half* __restrict__ Wt  = g_wth + (size_t)mn * 9 * 128 * 512;

    const int arow = tid >> 1;
    const int ahb  = (tid & 1) * 16;

    float acc[2][6][4];
#pragma unroll
    for (int i = 0; i < 2; i++)
#pragma unroll
        for (int j = 0; j < 6; j++)
#pragma unroll
            for (int k = 0; k < 4; k++) acc[i][j][k] = 0.f;

#define STAGE(S, BUF) do {                                                    \
    int tap_ = (S) >> 4;                                                      \
    int cc_  = ((S) & 15) * 32;                                               \
    int dy_  = (tap_ / 3 - 1) * dil;                                          \
    int dx_  = (tap_ % 3 - 1) * dil;                                          \
    { const __half* wsrc = Wt + ((size_t)(tap_ * 128) + arow) * 512 + cc_ + ahb; \
      uint4 v0 = *(const uint4*)(wsrc);                                       \
      uint4 v1 = *(const uint4*)(wsrc + 8);                                   \
      __half* ad = &smA[BUF][arow * PA_H + ahb];                              \
      *(uint4*)(ad) = v0; *(uint4*)(ad + 8) = v1; }                           \
    _Pragma("unroll")                                                         \
    for (int pb = 0; pb < 3; pb++) {                                          \
        int posl = lane + 32 * pb;                                            \
        int ry = posl / 48;                                                   \
        int x  = posl - ry * 48;                                              \
        int xs = x + dx_, ys = y0 + ry + dy_;                                 \
        bool ok = ((unsigned)xs < 48u) && ((unsigned)ys < 48u);               \
        int goff = ys * 48 + xs;                                              \
        _Pragma("unroll")                                                     \
        for (int pp = 0; pp < 2; pp++) {                                      \
            int cp = wid + 8 * pp;                                            \
            half2 v = __floats2half2_rn(0.f, 0.f);                            \
            if (ok)                                                           \
                v = *(const half2*)&inh[((size_t)((cc_ >> 1) + cp) * NPOS + goff) * 2]; \
            *(half2*)&smB[BUF][posl * PB_H + 2 * cp] = v;                     \
        }                                                                     \
    }                                                                         \
} while (0)

    STAGE(0, 0);
    __syncthreads();

    const int m0 = wm * 32;
    const int n0 = wn * 48;
    const int arow0 = lane >> 2;
    const int acol0 = lane & 3;
    const int brow0 = lane & 3;
    const int bcol0 = lane >> 2;

    for (int s = 0; s < 144; s++) {
        int buf = s & 1;
        if (s + 1 < 144) STAGE(s + 1, buf ^ 1);

        const __half* A_ = smA[buf];
        const __half* B_ = smB[buf];
#pragma unroll
        for (int k0 = 0; k0 < 32; k0 += 16) {
            uint32_t af[2][4];
#pragma unroll
            for (int mt = 0; mt < 2; mt++) {
                int r = m0 + mt * 16 + arow0;
                af[mt][0] = *(const uint32_t*)&A_[r * PA_H + k0 + 2 * acol0];
                af[mt][1] = *(const uint32_t*)&A_[(r + 8) * PA_H + k0 + 2 * acol0];
                af[mt][2] = *(const uint32_t*)&A_[r * PA_H + k0 + 2 * acol0 + 8];
                af[mt][3] = *(const uint32_t*)&A_[(r + 8) * PA_H + k0 + 2 * acol0 + 8];
            }
#pragma unroll
            for (int nt = 0; nt < 6; nt++) {
                int ncol = n0 + nt * 8 + bcol0;
                uint32_t bf[2];
                bf[0] = *(const uint32_t*)&B_[ncol * PB_H + k0 + 2 * brow0];
                bf[1] = *(const uint32_t*)&B_[ncol * PB_H + k0 + 2 * brow0 + 8];
                mma_f16(acc[0][nt], af[0], bf);
                mma_f16(acc[1][nt], af[1], bf);
            }
        }
        __syncthreads();
    }

    const float* sc = (mod ? sD : sR) + node * 128;
    const float* bi = (mod ? bD : bR) + node * 128;
    float* outp = out + ((size_t)((mod * 2 + b) * 4 + node) * 128) * NPOS + y0 * 48;

#pragma unroll
    for (int mt = 0; mt < 2; mt++) {
#pragma unroll
        for (int half = 0; half < 2; half++) {
            int co = m0 + mt * 16 + half * 8 + (lane >> 2);
            float s = __ldg(sc + co), bb = __ldg(bi + co);
            float* orow = outp + (size_t)co * NPOS;
#pragma unroll
            for (int nt = 0; nt < 6; nt++) {
                int pos = n0 + nt * 8 + (lane & 3) * 2;
                float v0 = fmaxf(fmaf(acc[mt][nt][half * 2 + 0], s, bb), 0.f);
                float v1 = fmaxf(fmaf(acc[mt][nt][half * 2 + 1], s, bb), 0.f);
                *(float2*)(orow + pos) = make_float2(v0, v1);
            }
        }
    }
#undef STAGE
}

// ---------------------------------------------------------------------------
// PA: register-resident cross-modal gating (proven)
// ---------------------------------------------------------------------------
__global__ __launch_bounds__(256)
void pa_kernel(float* __restrict__ feat, const float* __restrict__ paw)
{
    const int pl = threadIdx.x & 63;
    const int cs = threadIdx.x >> 6;
    const int bn  = blockIdx.x / 36;
    const int pos = (blockIdx.x % 36) * 64 + pl;
    float* pr = feat + (size_t)bn * 128 * NPOS + pos;
    float* pd = feat + (size_t)(8 + bn) * 128 * NPOS + pos;

    float r[32], d[32];
#pragma unroll 8
    for (int j = 0; j < 32; j++) {
        int c = cs * 32 + j;
        r[j] = pr[(size_t)c * NPOS];
        d[j] = pd[(size_t)c * NPOS];
    }

    __shared__ float red[2][4][2][64];

#pragma unroll
    for (int it = 0; it < 2; it++) {
        float s0 = 0.f, s1 = 0.f;
#pragma unroll 8
        for (int j = 0; j < 32; j++) {
            int c = cs * 32 + j;
            float df = r[j] - d[j];
            s0 = fmaf(df,  __ldg(paw + c),       s0);
            s1 = fmaf(-df, __ldg(paw + 128 + c), s1);
        }
        red[it][cs][0][pl] = s0;
        red[it][cs][1][pl] = s1;
        __syncthreads();
        float S0 = red[it][0][0][pl] + red[it][1][0][pl] + red[it][2][0][pl] + red[it][3][0][pl];
        float S1 = red[it][0][1][pl] + red[it][1][1][pl] + red[it][2][1][pl] + red[it][3][1][pl];
        float g0 = sigm(S0), g1 = sigm(S1);
#pragma unroll 8
        for (int j = 0; j < 32; j++) {
            float t = r[j];
            r[j] = fmaf(d[j], g1, t);
            d[j] = fmaf(t, g0, d[j]);
        }
    }

#pragma unroll 8
    for (int j = 0; j < 32; j++) {
        int c = cs * 32 + j;
        pr[(size_t)c * NPOS] = r[j];
        pd[(size_t)c * NPOS] = d[j];
    }
}

// ---------------------------------------------------------------------------
// g1a: edge gates (proven)
// ---------------------------------------------------------------------------
__global__ __launch_bounds__(256)
void g1a_kernel(const float* __restrict__ dout, int it,
                const float* __restrict__ wgtR, const float* __restrict__ wgtD)
{
    const float* feat = it ? g_feat2 : dout;
    const int pl = threadIdx.x & 63;
    const int cs = threadIdx.x >> 6;
    const int pos = blockIdx.x * 64 + pl;
    const int b = blockIdx.y, mod = blockIdx.z;
    const float* wgt = mod ? wgtD : wgtR;
    const int modb = mod * 2 + b;
    size_t base = (size_t)(modb * 4) * 128 * NPOS;
    const float* f = feat + base + pos;

    float s[3][4];
#pragma unroll
    for (int k = 0; k < 3; k++)
#pragma unroll
        for (int p = 0; p < 4; p++) s[k][p] = 0.f;

#pragma unroll 4
    for (int j = 0; j < 32; j++) {
        int c = cs * 32 + j;
        float w0 = __ldg(wgt + c), w1 = __ldg(wgt + 128 + c), w2 = __ldg(wgt + 256 + c);
#pragma unroll
        for (int p = 0; p < 4; p++) {
            float fv = f[(size_t)(p * 128 + c) * NPOS];
            s[0][p] = fmaf(w0, fv, s[0][p]);
            s[1][p] = fmaf(w1, fv, s[1][p]);
            s[2][p] = fmaf(w2, fv, s[2][p]);
        }
    }

    __shared__ float red[4][12][64];
#pragma unroll
    for (int k = 0; k < 3; k++)
#pragma unroll
        for (int p = 0; p < 4; p++)
            red[cs][k * 4 + p][pl] = s[k][p];
    __syncthreads();

    if (threadIdx.x < 64) {
        float ss[12];
#pragma unroll
        for (int j = 0; j < 12; j++)
            ss[j] = red[0][j][pl] + red[1][j][pl] + red[2][j][pl] + red[3][j][pl];

        const int OI[4][3] = {{1,2,3},{0,2,3},{0,1,3},{0,1,2}};
#pragma unroll
        for (int i = 0; i < 4; i++)
#pragma unroll
            for (int k = 0; k < 3; k++) {
                float sg = sigm(ss[k * 4 + i] - ss[k * 4 + OI[i][k]]);
                g_gate[(size_t)(modb * 12 + i * 3 + k) * NPOS + pos] = sg;
            }
    }
}

// ---------------------------------------------------------------------------
// g1b: messages (proven)
// ---------------------------------------------------------------------------
__global__ __launch_bounds__(256)
void g1b_kernel(const float* __restrict__ dout, int it)
{
    const float* feat = it ? g_feat2 : dout;
    const int c   = blockIdx.x / 9;
    const int pos = (blockIdx.x % 9) * 256 + threadIdx.x;
    const int b = blockIdx.y, mod = blockIdx.z;
    const int modb = mod * 2 + b;
    size_t base = (size_t)(modb * 4) * 128 * NPOS;
    const float* f = feat + base + (size_t)c * NPOS + pos;

    float fv[4];
#pragma unroll
    for (int p = 0; p < 4; p++) fv[p] = f[(size_t)(p * 128) * NPOS];

    float sg[12];
#pragma unroll
    for (int g = 0; g < 12; g++)
        sg[g] = g_gate[(size_t)(modb * 12 + g) * NPOS + pos];

    const int OI[4][3] = {{1,2,3},{0,2,3},{0,1,3},{0,1,2}};
    const int c3 = c % 3;
    float* mo = g_m + base + (size_t)c * NPOS + pos;
#pragma unroll
    for (int i = 0; i < 4; i++) {
        float msum = 0.f;
#pragma unroll
        for (int k = 0; k < 3; k++) {
            int gi = 2 * k + c3;
            if (gi >= 3) gi -= 3;
            if (gi >= 3) gi -= 3;
            msum = fmaf(fv[OI[i][k]], sg[i * 3 + gi], msum);
        }
        mo[(size_t)(i * 128) * NPOS] = msum;
    }
}

// ---------------------------------------------------------------------------
// g2 via mma.sync fp16: z,r = sigmoid(W01 @ [m;feat] + b01)
// grid: (24 colblk, 2 oblk, 16 modbn), 256 thr, CTA 128o x 96col, K=256.
// ---------------------------------------------------------------------------
__global__ __launch_bounds__(256)
void g2_mma_kernel(const float* __restrict__ dout, int it,
                   const float* __restrict__ gbR, const float* __restrict__ gbD)
{
    __shared__ __half smA[2][A_BUF_H];
    __shared__ __half smB[2][B_BUF_H];

    const float* feat = it ? g_feat2 : dout;
    const int tid = threadIdx.x;
    const int lane = tid & 31;
    const int wid = tid >> 5;
    const int wm = wid & 3;
    const int wn = wid >> 2;

    const int zid = blockIdx.z;
    const int mod = zid >> 3, bn = zid & 7;
    const int oblk = blockIdx.y;
    const int col0 = blockIdx.x * 96;

    const __half* Agw = g_gwh + (size_t)mod * 3 * 128 * 256 + (size_t)oblk * 128 * 256;
    const float* bias = (mod ? gbD : gbR) + oblk * 128;
    size_t base = (size_t)(mod * 8 + bn) * 128 * NPOS;
    const float* F = feat + base;
    const float* M = g_m + base;

    const int arow = tid >> 1;
    const int ahb  = (tid & 1) * 16;

    float acc[2][6][4];
#pragma unroll
    for (int i = 0; i < 2; i++)
#pragma unroll
        for (int j = 0; j < 6; j++)
#pragma unroll
            for (int k = 0; k < 4; k++) acc[i][j][k] = 0.f;

#define GSTAGE(S, BUF) do {                                                   \
    int cc_ = (S) * 32;                                                       \
    { const __half* wsrc = Agw + (size_t)arow * 256 + cc_ + ahb;              \
      uint4 v0 = *(const uint4*)(wsrc);                                       \
      uint4 v1 = *(const uint4*)(wsrc + 8);                                   \
      __half* ad = &smA[BUF][arow * PA_H + ahb];                              \
      *(uint4*)(ad) = v0; *(uint4*)(ad + 8) = v1; }                           \
    _Pragma("unroll")                                                         \
    for (int pb = 0; pb < 3; pb++) {                                          \
        int col = lane + 32 * pb;                                             \
        _Pragma("unroll")                                                     \
        for (int pp = 0; pp < 2; pp++) {                                      \
            int x = cc_ + 2 * (wid + 8 * pp);                                 \
            float v0, v1;                                                     \
            if (x < 128) {                                                    \
                v0 = M[(size_t)x * NPOS + col0 + col];                        \
                v1 = M[(size_t)(x + 1) * NPOS + col0 + col];                  \
            } else {                                                          \
                v0 = F[(size_t)(x - 128) * NPOS + col0 + col];                \
                v1 = F[(size_t)(x - 127) * NPOS + col0 + col];                \
            }                                                                 \
            *(half2*)&smB[BUF][col * PB_H + (x - cc_)] = __floats2half2_rn(v0, v1); \
        }                                                                     \
    }                                                                         \
} while (0)

    GSTAGE(0, 0);
    __syncthreads();

    const int m0 = wm * 32;
    const int n0 = wn * 48;
    const int arow0 = lane >> 2;
    const int acol0 = lane & 3;
    const int brow0 = lane & 3;
    const int bcol0 = lane >> 2;

    for (int s = 0; s < 8; s++) {
        int buf = s & 1;
        if (s + 1 < 8) GSTAGE(s + 1, buf ^ 1);

        const __half* A_ = smA[buf];
        const __half* B_ = smB[buf];
#pragma unroll
        for (int k0 = 0; k0 < 32; k0 += 16) {
            uint32_t af[2][4];
#pragma unroll
            for (int mt = 0; mt < 2; mt++) {
                int r = m0 + mt * 16 + arow0;
                af[mt][0] = *(const uint32_t*)&A_[r * PA_H + k0 + 2 * acol0];
                af[mt][1] = *(const uint32_t*)&A_[(r + 8) * PA_H + k0 + 2 * acol0];
                af[mt][2] = *(const uint32_t*)&A_[r * PA_H + k0 + 2 * acol0 + 8];
                af[mt][3] = *(const uint32_t*)&A_[(r + 8) * PA_H + k0 + 2 * acol0 + 8];
            }
#pragma unroll
            for (int nt = 0; nt < 6; nt++) {
                int ncol = n0 + nt * 8 + bcol0;
                uint32_t bf[2];
                bf[0] = *(const uint32_t*)&B_[ncol * PB_H + k0 + 2 * brow0];
                bf[1] = *(const uint32_t*)&B_[ncol * PB_H + k0 + 2 * brow0 + 8];
                mma_f16(acc[0][nt], af[0], bf);
                mma_f16(acc[1][nt], af[1], bf);
            }
        }
        __syncthreads();
    }

    float* ob = (oblk == 0) ? (g_z + base) : (g_r + base);
#pragma unroll
    for (int mt = 0; mt < 2; mt++) {
#pragma unroll
        for (int half = 0; half < 2; half++) {
            int o = m0 + mt * 16 + half * 8 + (lane >> 2);
            float bv = __ldg(bias + o);
            float* orow = ob + (size_t)o * NPOS + col0;
#pragma unroll
            for (int nt = 0; nt < 6; nt++) {
                int col = n0 + nt * 8 + (lane & 3) * 2;
                orow[col]     = sigm(acc[mt][nt][half * 2 + 0] + bv);
                orow[col + 1] = sigm(acc[mt][nt][half * 2 + 1] + bv);
            }
        }
    }
#undef GSTAGE
}

// ---------------------------------------------------------------------------
// g3 via mma.sync fp16: cand = tanh(W2 @ [m; feat*r] + b2), fused GRU update
// grid: (24 colblk, 1, 16 modbn), 256 thr, CTA 128o x 96col, K=256.
// ---------------------------------------------------------------------------
__global__ __launch_bounds__(256)
void g3_mma_kernel(float* __restrict__ dout, int it,
                   const float* __restrict__ gbR, const float* __restrict__ gbD,
                   const float* __restrict__ gamR, const float* __restrict__ gamD)
{
    __shared__ __half smA[2][A_BUF_H];
    __shared__ __half smB[2][B_BUF_H];

    const float* feat = it ? g_feat2 : dout;
    float* dst        = it ? dout : g_feat2;
    const int tid = threadIdx.x;
    const int lane = tid & 31;
    const int wid = tid >> 5;
    const int wm = wid & 3;
    const int wn = wid >> 2;

    const int zid = blockIdx.z;
    const int mod = zid >> 3, bn = zid & 7;
    const int col0 = blockIdx.x * 96;

    const __half* Agw = g_gwh + (size_t)mod * 3 * 128 * 256 + (size_t)2 * 128 * 256;
    const float* bias = (mod ? gbD : gbR) + 2 * 128;
    float gam = mod ? __ldg(gamD) : __ldg(gamR);
    size_t base = (size_t)(mod * 8 + bn) * 128 * NPOS;
    const float* F = feat + base;
    const float* M = g_m + base;
    const float* R = g_r + base;

    const int arow = tid >> 1;
    const int ahb  = (tid & 1) * 16;

    float acc[2][6][4];
#pragma unroll
    for (int i = 0; i < 2; i++)
#pragma unroll
        for (int j = 0; j < 6; j++)
#pragma unroll
            for (int k = 0; k < 4; k++) acc[i][j][k] = 0.f;

#define G3STAGE(S, BUF) do {                                                  \
    int cc_ = (S) * 32;                                                       \
    { const __half* wsrc = Agw + (size_t)arow * 256 + cc_ + ahb;              \
      uint4 v0 = *(const uint4*)(wsrc);                                       \
      uint4 v1 = *(const uint4*)(wsrc + 8);                                   \
      __half* ad = &smA[BUF][arow * PA_H + ahb];                              \
      *(uint4*)(ad) = v0; *(uint4*)(ad + 8) = v1; }                           \
    _Pragma("unroll")                                                         \
    for (int pb = 0; pb < 3; pb++) {                                          \
        int col = lane + 32 * pb;                                             \
        _Pragma("unroll")                                                     \
        for (int pp = 0; pp < 2; pp++) {                                      \
            int x = cc_ + 2 * (wid + 8 * pp);                                 \
            float v0, v1;                                                     \
            if (x < 128) {                                                    \
                v0 = M[(size_t)x * NPOS + col0 + col];                        \
                v1 = M[(size_t)(x + 1) * NPOS + col0 + col];                  \
            } else {                                                          \
                size_t i0 = (size_t)(x - 128) * NPOS + col0 + col;            \
                size_t i1 = (size_t)(x - 127) * NPOS + col0 + col;            \
                v0 = F[i0] * R[i0];                                           \
                v1 = F[i1] * R[i1];                                           \
            }                                                                 \
            *(half2*)&smB[BUF][col * PB_H + (x - cc_)] = __floats2half2_rn(v0, v1); \
        }                                                                     \
    }                                                                         \
} while (0)

    G3STAGE(0, 0);
    __syncthreads();

    const int m0 = wm * 32;
    const int n0 = wn * 48;
    const int arow0 = lane >> 2;
    const int acol0 = lane & 3;
    const int brow0 = lane & 3;
    const int bcol0 = lane >> 2;

    for (int s = 0; s < 8; s++) {
        int buf = s & 1;
        if (s + 1 < 8) G3STAGE(s + 1, buf ^ 1);

        const __half* A_ = smA[buf];
        const __half* B_ = smB[buf];
#pragma unroll
        for (int k0 = 0; k0 < 32; k0 += 16) {
            uint32_t af[2][4];
#pragma unroll
            for (int mt = 0; mt < 2; mt++) {
                int r = m0 + mt * 16 + arow0;
                af[mt][0] = *(const uint32_t*)&A_[r * PA_H + k0 + 2 * acol0];
                af[mt][1] = *(const uint32_t*)&A_[(r + 8) * PA_H + k0 + 2 * acol0];
                af[mt][2] = *(const uint32_t*)&A_[r * PA_H + k0 + 2 * acol0 + 8];
                af[mt][3] = *(const uint32_t*)&A_[(r + 8) * PA_H + k0 + 2 * acol0 + 8];
            }
#pragma unroll
            for (int nt = 0; nt < 6; nt++) {
                int ncol = n0 + nt * 8 + bcol0;
                uint32_t bf[2];
                bf[0] = *(const uint32_t*)&B_[ncol * PB_H + k0 + 2 * brow0];
                bf[1] = *(const uint32_t*)&B_[ncol * PB_H + k0 + 2 * brow0 + 8];
                mma_f16(acc[0][nt], af[0], bf);
                mma_f16(acc[1][nt], af[1], bf);
            }
        }
        __syncthreads();
    }

#pragma unroll
    for (int mt = 0; mt < 2; mt++) {
#pragma unroll
        for (int half = 0; half < 2; half++) {
            int o = m0 + mt * 16 + half * 8 + (lane >> 2);
            float bv = __ldg(bias + o);
#pragma unroll
            for (int nt = 0; nt < 6; nt++) {
                int col = col0 + n0 + nt * 8 + (lane & 3) * 2;
#pragma unroll
                for (int u = 0; u < 2; u++) {
                    size_t idx = base + (size_t)o * NPOS + col + u;
                    float cand = tanhf(acc[mt][nt][half * 2 + u] + bv);
                    float z = g_z[idx];
                    float f = feat[idx];
                    dst[idx] = fmaf(gam, fmaf(f, 1.f - z, cand * z), f);
                }
            }
        }
    }
#undef G3STAGE
}

// ---------------------------------------------------------------------------
extern "C" void kernel_launch(void* const* d_in, const int* in_sizes, int n_in,
                              void* d_out, int out_size)
{
    const float* feat_rgb = (const float*)d_in[0];
    const float* feat_dep = (const float*)d_in[1];
    const float* ppm_w_r  = (const float*)d_in[2];
    const float* ppm_s_r  = (const float*)d_in[3];
    const float* ppm_b_r  = (const float*)d_in[4];
    const float* ppm_w_d  = (const float*)d_in[5];
    const float* ppm_s_d  = (const float*)d_in[6];
    const float* ppm_b_d  = (const float*)d_in[7];
    const float* pa_w     = (const float*)d_in[8];
    const float* wgt_r    = (const float*)d_in[9];
    const float* gruw_r   = (const float*)d_in[10];
    const float* grub_r   = (const float*)d_in[11];
    const float* gam_r    = (const float*)d_in[12];
    const float* wgt_d    = (const float*)d_in[13];
    const float* gruw_d   = (const float*)d_in[14];
    const float* grub_d   = (const float*)d_in[15];
    const float* gam_d    = (const float*)d_in[16];
    float* out = (float*)d_out;

    wt_prep_kernel<<<(2*4*9*128*512 + 255) / 256, 256>>>(ppm_w_r, ppm_w_d);
    gwh_prep_kernel<<<(2*3*128*256 + 255) / 256, 256>>>(gruw_r, gruw_d);
    in_prep_kernel<<<(4*256*NPOS + 255) / 256, 256>>>(feat_rgb, feat_dep);
    conv_mma_kernel<<<dim3(48, 8), 256>>>(ppm_s_r, ppm_b_r, ppm_s_d, ppm_b_d, out);
    pa_kernel<<<288, 256>>>(out, pa_w);
    for (int it = 0; it < 2; it++) {
        g1a_kernel<<<dim3(36, 2, 2), 256>>>(out, it, wgt_r, wgt_d);
        g1b_kernel<<<dim3(1152, 2, 2), 256>>>(out, it);
        g2_mma_kernel<<<dim3(24, 2, 16), 256>>>(out, it, grub_r, grub_d);
        g3_mma_kernel<<<dim3(24, 1, 16), 256>>>(out, it, grub_r, grub_d,
                                                gam_r, gam_d);
    }
}

// round 10
// speedup vs baseline: 5.9422x; 1.0325x over previous
#include <cuda_runtime.h>
#include <cuda_fp16.h>
#include <math.h>
#include <stdint.h>

#define NPOS 2304
#define FEATSZ (2*2*4*128*NPOS)

// Scratch
__device__ float  g_feat2[FEATSZ];
__device__ float  g_m[FEATSZ];
__device__ float  g_z[FEATSZ];
__device__ float  g_r[FEATSZ];
__device__ __half g_wth[2*4*9*128*512];  // conv weights [mn][tap][co][ci], fp16
__device__ __half g_gwh[2*3*128*256];    // gru weights  [mod][gate][o][k], fp16
__device__ __half g_inh[2*2*512*NPOS];   // conv input   [mb][cpair][pos][2], fp16
__device__ float  g_gate[2*2*12*NPOS];   // edge gates   [modb][i*3+k][pos]

__device__ __forceinline__ float sigm(float x) { return 1.f / (1.f + expf(-x)); }

__device__ __forceinline__ void mma_f16(float* c, const uint32_t* a, const uint32_t* b) {
    asm volatile(
        "mma.sync.aligned.m16n8k16.row.col.f32.f16.f16.f32 "
        "{%0,%1,%2,%3}, {%4,%5,%6,%7}, {%8,%9}, {%0,%1,%2,%3};"
        : "+f"(c[0]), "+f"(c[1]), "+f"(c[2]), "+f"(c[3])
        : "r"(a[0]), "r"(a[1]), "r"(a[2]), "r"(a[3]), "r"(b[0]), "r"(b[1]));
}

#define CPA16(dst, src) \
    asm volatile("cp.async.cg.shared.global [%0], [%1], 16;" :: "r"(dst), "l"(src))
#define CPA4(dst, src, nbytes) \
    asm volatile("cp.async.ca.shared.global [%0], [%1], 4, %2;" \
                 :: "r"(dst), "l"(src), "r"(nbytes))
#define CPA_COMMIT() asm volatile("cp.async.commit_group;" ::: "memory")
#define CPA_WAIT1()  asm volatile("cp.async.wait_group 1;" ::: "memory")
#define CPA_WAIT0()  asm volatile("cp.async.wait_group 0;" ::: "memory")

// ---------------------------------------------------------------------------
// Prep kernels
// ---------------------------------------------------------------------------
__global__ void wt_prep_kernel(const float* __restrict__ wR, const float* __restrict__ wD)
{
    int e = blockIdx.x * 256 + threadIdx.x;
    if (e >= 2*4*9*128*512) return;
    int ci = e & 511;
    int r = e >> 9;
    int co = r & 127; r >>= 7;
    int tap = r % 9; r /= 9;
    int node = r & 3;
    int mod = r >> 2;
    const float* w = mod ? wD : wR;
    g_wth[e] = __float2half_rn(w[((size_t)(node*128 + co)*512 + ci)*9 + tap]);
}

__global__ void gwh_prep_kernel(const float* __restrict__ gwR, const float* __restrict__ gwD)
{
    int e = blockIdx.x * 256 + threadIdx.x;
    if (e >= 2*3*128*256) return;
    int mod = e / (3*128*256);
    int x   = e % (3*128*256);
    const float* w = mod ? gwD : gwR;
    g_gwh[e] = __float2half_rn(w[x]);
}

// channel-pair interleave: g_inh[((mb*256 + cp)*NPOS + pos)*2 + {0,1}]
__global__ void in_prep_kernel(const float* __restrict__ inR, const float* __restrict__ inD)
{
    int e = blockIdx.x * 256 + threadIdx.x;
    if (e >= 4 * 256 * NPOS) return;
    int pos = e % NPOS;
    int r = e / NPOS;
    int cp = r & 255;
    int mb = r >> 8;                 // mod*2 + b
    const float* src = ((mb >> 1) ? inD : inR)
                     + ((size_t)(mb & 1) * 512 + 2 * cp) * NPOS + pos;
    *(half2*)&g_inh[((size_t)(mb * 256 + cp) * NPOS + pos) * 2] =
        __floats2half2_rn(src[0], src[NPOS]);
}

// ---------------------------------------------------------------------------
// Conv via mma.sync fp16 m16n8k16 implicit GEMM; cp.async staging.
// grid: (48 = b*24 + rowpair, 8 = mod*4+node), 256 threads (8 warps: 4m x 2n)
// ---------------------------------------------------------------------------
#define PA_H 40
#define PB_H 40
#define A_BUF_H (128*PA_H)
#define B_BUF_H (96*PB_H)

__global__ __launch_bounds__(256)
void conv_mma_kernel(const float* __restrict__ sR, const float* __restrict__ bR,
                     const float* __restrict__ sD, const float* __restrict__ bD,
                     float* __restrict__ out)
{
    __shared__ __half smA[2][A_BUF_H];
    __shared__ __half smB[2][B_BUF_H];

    const int tid = threadIdx.x;
    const int lane = tid & 31;
    const int wid = tid >> 5;
    const int wm = wid & 3;
    const int wn = wid >> 2;

    const int mn   = blockIdx.y;
    const int mod  = mn >> 2, node = mn & 3;
    const int dil  = 1 << node;
    const int b    = blockIdx.x / 24;
    const int y0   = (blockIdx.x % 24) * 2;

    const __half* __restrict__ inh = g_inh + (size_t)(mod * 2 + b) * 256 * NPOS * 2;
    const __half* __restrict__ Wt  = g_wth + (size_t)mn * 9 * 128 * 512;

    const int arow = tid >> 1;
    const int ahb  = (tid & 1) * 16;

    const uint32_t smA_u32 = (uint32_t)__cvta_generic_to_shared(&smA[0][0]);
    const uint32_t smB_u32 = (uint32_t)__cvta_generic_to_shared(&smB[0][0]);

    float acc[2][6][4];
#pragma unroll
    for (int i = 0; i < 2; i++)
#pragma unroll
        for (int j = 0; j < 6; j++)
#pragma unroll
            for (int k = 0; k < 4; k++) acc[i][j][k] = 0.f;

#define STAGE(S, BUF) do {                                                    \
    int tap_ = (S) >> 4;                                                      \
    int cc_  = ((S) & 15) * 32;                                               \
    int dy_  = (tap_ / 3 - 1) * dil;                                          \
    int dx_  = (tap_ % 3 - 1) * dil;                                          \
    { const __half* wsrc = Wt + ((size_t)(tap_ * 128) + arow) * 512 + cc_ + ahb; \
      uint32_t ad = smA_u32 + (uint32_t)(BUF) * (A_BUF_H * 2)                 \
                  + (uint32_t)(arow * PA_H + ahb) * 2;                        \
      CPA16(ad, wsrc); CPA16(ad + 16, wsrc + 8); }                            \
    _Pragma("unroll")                                                         \
    for (int pb = 0; pb < 3; pb++) {                                          \
        int posl = lane + 32 * pb;                                            \
        int ry = posl / 48;                                                   \
        int x  = posl - ry * 48;                                              \
        int xs = x + dx_, ys = y0 + ry + dy_;                                 \
        bool ok = ((unsigned)xs < 48u) && ((unsigned)ys < 48u);               \
        int goff = ok ? (ys * 48 + xs) : 0;                                   \
        uint32_t nb = ok ? 4u : 0u;                                           \
        _Pragma("unroll")                                                     \
        for (int pp = 0; pp < 2; pp++) {                                      \
            int cp = wid + 8 * pp;                                            \
            const __half* src = inh + ((size_t)((cc_ >> 1) + cp) * NPOS + goff) * 2; \
            uint32_t bd = smB_u32 + (uint32_t)(BUF) * (B_BUF_H * 2)           \
                        + (uint32_t)(posl * PB_H + 2 * cp) * 2;               \
            CPA4(bd, src, nb);                                                \
        }                                                                     \
    }                                                                         \
    CPA_COMMIT();                                                             \
} while (0)

    STAGE(0, 0);

    const int m0 = wm * 32;
    const int n0 = wn * 48;
    const int arow0 = lane >> 2;
    const int acol0 = lane & 3;
    const int brow0 = lane & 3;
    const int bcol0 = lane >> 2;

    for (int s = 0; s < 144; s++) {
        int buf = s & 1;
        if (s + 1 < 144) {
            STAGE(s + 1, buf ^ 1);
            CPA_WAIT1();                     // stage s complete (1 group in flight)
        } else {
            CPA_WAIT0();
        }
        __syncthreads();

        const __half* A_ = smA[buf];
        const __half* B_ = smB[buf];
#pragma unroll
        for (int k0 = 0; k0 < 32; k0 += 16) {
            uint32_t af[2][4];
#pragma unroll
            for (int mt = 0; mt < 2; mt++) {
                int r = m0 + mt * 16 + arow0;
                af[mt][0] = *(const uint32_t*)&A_[r * PA_H + k0 + 2 * acol0];
                af[mt][1] = *(const uint32_t*)&A_[(r + 8) * PA_H + k0 + 2 * acol0];
                af[mt][2] = *(const uint32_t*)&A_[r * PA_H + k0 + 2 * acol0 + 8];
                af[mt][3] = *(const uint32_t*)&A_[(r + 8) * PA_H + k0 + 2 * acol0 + 8];
            }
#pragma unroll
            for (int nt = 0; nt < 6; nt++) {
                int ncol = n0 + nt * 8 + bcol0;
                uint32_t bf[2];
                bf[0] = *(const uint32_t*)&B_[ncol * PB_H + k0 + 2 * brow0];
                bf[1] = *(const uint32_t*)&B_[ncol * PB_H + k0 + 2 * brow0 + 8];
                mma_f16(acc[0][nt], af[0], bf);
                mma_f16(acc[1][nt], af[1], bf);
            }
        }
        __syncthreads();                     // safe to overwrite buf next iter
    }

    const float* sc = (mod ? sD : sR) + node * 128;
    const float* bi = (mod ? bD : bR) + node * 128;
    float* outp = out + ((size_t)((mod * 2 + b) * 4 + node) * 128) * NPOS + y0 * 48;

#pragma unroll
    for (int mt = 0; mt < 2; mt++) {
#pragma unroll
        for (int half = 0; half < 2; half++) {
            int co = m0 + mt * 16 + half * 8 + (lane >> 2);
            float s = __ldg(sc + co), bb = __ldg(bi + co);
            float* orow = outp + (size_t)co * NPOS;
#pragma unroll
            for (int nt = 0; nt < 6; nt++) {
                int pos = n0 + nt * 8 + (lane & 3) * 2;
                float v0 = fmaxf(fmaf(acc[mt][nt][half * 2 + 0], s, bb), 0.f);
                float v1 = fmaxf(fmaf(acc[mt][nt][half * 2 + 1], s, bb), 0.f);
                *(float2*)(orow + pos) = make_float2(v0, v1);
            }
        }
    }
#undef STAGE
}

// ---------------------------------------------------------------------------
// PA: register-resident cross-modal gating (proven)
// ---------------------------------------------------------------------------
__global__ __launch_bounds__(256)
void pa_kernel(float* __restrict__ feat, const float* __restrict__ paw)
{
    const int pl = threadIdx.x & 63;
    const int cs = threadIdx.x >> 6;
    const int bn  = blockIdx.x / 36;
    const int pos = (blockIdx.x % 36) * 64 + pl;
    float* pr = feat + (size_t)bn * 128 * NPOS + pos;
    float* pd = feat + (size_t)(8 + bn) * 128 * NPOS + pos;

    float r[32], d[32];
#pragma unroll 8
    for (int j = 0; j < 32; j++) {
        int c = cs * 32 + j;
        r[j] = pr[(size_t)c * NPOS];
        d[j] = pd[(size_t)c * NPOS];
    }

    __shared__ float red[2][4][2][64];

#pragma unroll
    for (int it = 0; it < 2; it++) {
        float s0 = 0.f, s1 = 0.f;
#pragma unroll 8
        for (int j = 0; j < 32; j++) {
            int c = cs * 32 + j;
            float df = r[j] - d[j];
            s0 = fmaf(df,  __ldg(paw + c),       s0);
            s1 = fmaf(-df, __ldg(paw + 128 + c), s1);
        }
        red[it][cs][0][pl] = s0;
        red[it][cs][1][pl] = s1;
        __syncthreads();
        float S0 = red[it][0][0][pl] + red[it][1][0][pl] + red[it][2][0][pl] + red[it][3][0][pl];
        float S1 = red[it][0][1][pl] + red[it][1][1][pl] + red[it][2][1][pl] + red[it][3][1][pl];
        float g0 = sigm(S0), g1 = sigm(S1);
#pragma unroll 8
        for (int j = 0; j < 32; j++) {
            float t = r[j];
            r[j] = fmaf(d[j], g1, t);
            d[j] = fmaf(t, g0, d[j]);
        }
    }

#pragma unroll 8
    for (int j = 0; j < 32; j++) {
        int c = cs * 32 + j;
        pr[(size_t)c * NPOS] = r[j];
        pd[(size_t)c * NPOS] = d[j];
    }
}

// ---------------------------------------------------------------------------
// g1a: edge gates (proven)
// ---------------------------------------------------------------------------
__global__ __launch_bounds__(256)
void g1a_kernel(const float* __restrict__ dout, int it,
                const float* __restrict__ wgtR, const float* __restrict__ wgtD)
{
    const float* feat = it ? g_feat2 : dout;
    const int pl = threadIdx.x & 63;
    const int cs = threadIdx.x >> 6;
    const int pos = blockIdx.x * 64 + pl;
    const int b = blockIdx.y, mod = blockIdx.z;
    const float* wgt = mod ? wgtD : wgtR;
    const int modb = mod * 2 + b;
    size_t base = (size_t)(modb * 4) * 128 * NPOS;
    const float* f = feat + base + pos;

    float s[3][4];
#pragma unroll
    for (int k = 0; k < 3; k++)
#pragma unroll
        for (int p = 0; p < 4; p++) s[k][p] = 0.f;

#pragma unroll 4
    for (int j = 0; j < 32; j++) {
        int c = cs * 32 + j;
        float w0 = __ldg(wgt + c), w1 = __ldg(wgt + 128 + c), w2 = __ldg(wgt + 256 + c);
#pragma unroll
        for (int p = 0; p < 4; p++) {
            float fv = f[(size_t)(p * 128 + c) * NPOS];
            s[0][p] = fmaf(w0, fv, s[0][p]);
            s[1][p] = fmaf(w1, fv, s[1][p]);
            s[2][p] = fmaf(w2, fv, s[2][p]);
        }
    }

    __shared__ float red[4][12][64];
#pragma unroll
    for (int k = 0; k < 3; k++)
#pragma unroll
        for (int p = 0; p < 4; p++)
            red[cs][k * 4 + p][pl] = s[k][p];
    __syncthreads();

    if (threadIdx.x < 64) {
        float ss[12];
#pragma unroll
        for (int j = 0; j < 12; j++)
            ss[j] = red[0][j][pl] + red[1][j][pl] + red[2][j][pl] + red[3][j][pl];

        const int OI[4][3] = {{1,2,3},{0,2,3},{0,1,3},{0,1,2}};
#pragma unroll
        for (int i = 0; i < 4; i++)
#pragma unroll
            for (int k = 0; k < 3; k++) {
                float sg = sigm(ss[k * 4 + i] - ss[k * 4 + OI[i][k]]);
                g_gate[(size_t)(modb * 12 + i * 3 + k) * NPOS + pos] = sg;
            }
    }
}

// ---------------------------------------------------------------------------
// g1b: messages (proven)
// ---------------------------------------------------------------------------
__global__ __launch_bounds__(256)
void g1b_kernel(const float* __restrict__ dout, int it)
{
    const float* feat = it ? g_feat2 : dout;
    const int c   = blockIdx.x / 9;
    const int pos = (blockIdx.x % 9) * 256 + threadIdx.x;
    const int b = blockIdx.y, mod = blockIdx.z;
    const int modb = mod * 2 + b;
    size_t base = (size_t)(modb * 4) * 128 * NPOS;
    const float* f = feat + base + (size_t)c * NPOS + pos;

    float fv[4];
#pragma unroll
    for (int p = 0; p < 4; p++) fv[p] = f[(size_t)(p * 128) * NPOS];

    float sg[12];
#pragma unroll
    for (int g = 0; g < 12; g++)
        sg[g] = g_gate[(size_t)(modb * 12 + g) * NPOS + pos];

    const int OI[4][3] = {{1,2,3},{0,2,3},{0,1,3},{0,1,2}};
    const int c3 = c % 3;
    float* mo = g_m + base + (size_t)c * NPOS + pos;
#pragma unroll
    for (int i = 0; i < 4; i++) {
        float msum = 0.f;
#pragma unroll
        for (int k = 0; k < 3; k++) {
            int gi = 2 * k + c3;
            if (gi >= 3) gi -= 3;
            if (gi >= 3) gi -= 3;
            msum = fmaf(fv[OI[i][k]], sg[i * 3 + gi], msum);
        }
        mo[(size_t)(i * 128) * NPOS] = msum;
    }
}

// ---------------------------------------------------------------------------
// g2 via mma.sync fp16: z,r = sigmoid(W01 @ [m;feat] + b01)  (proven)
// ---------------------------------------------------------------------------
__global__ __launch_bounds__(256)
void g2_mma_kernel(const float* __restrict__ dout, int it,
                   const float* __restrict__ gbR, const float* __restrict__ gbD)
{
    __shared__ __half smA[2][A_BUF_H];
    __shared__ __half smB[2][B_BUF_H];

    const float* feat = it ? g_feat2 : dout;
    const int tid = threadIdx.x;
    const int lane = tid & 31;
    const int wid = tid >> 5;
    const int wm = wid & 3;
    const int wn = wid >> 2;

    const int zid = blockIdx.z;
    const int mod = zid >> 3, bn = zid & 7;
    const int oblk = blockIdx.y;
    const int col0 = blockIdx.x * 96;

    const __half* Agw = g_gwh + (size_t)mod * 3 * 128 * 256 + (size_t)oblk * 128 * 256;
    const float* bias = (mod ? gbD : gbR) + oblk * 128;
    size_t base = (size_t)(mod * 8 + bn) * 128 * NPOS;
    const float* F = feat + base;
    const float* M = g_m + base;

    const int arow = tid >> 1;
    const int ahb  = (tid & 1) * 16;

    float acc[2][6][4];
#pragma unroll
    for (int i = 0; i < 2; i++)
#pragma unroll
        for (int j = 0; j < 6; j++)
#pragma unroll
            for (int k = 0; k < 4; k++) acc[i][j][k] = 0.f;

#define GSTAGE(S, BUF) do {                                                   \
    int cc_ = (S) * 32;                                                       \
    { const __half* wsrc = Agw + (size_t)arow * 256 + cc_ + ahb;              \
      uint4 v0 = *(const uint4*)(wsrc);                                       \
      uint4 v1 = *(const uint4*)(wsrc + 8);                                   \
      __half* ad = &smA[BUF][arow * PA_H + ahb];                              \
      *(uint4*)(ad) = v0; *(uint4*)(ad + 8) = v1; }                           \
    _Pragma("unroll")                                                         \
    for (int pb = 0; pb < 3; pb++) {                                          \
        int col = lane + 32 * pb;                                             \
        _Pragma("unroll")                                                     \
        for (int pp = 0; pp < 2; pp++) {                                      \
            int x = cc_ + 2 * (wid + 8 * pp);                                 \
            float v0, v1;                                                     \
            if (x < 128) {                                                    \
                v0 = M[(size_t)x * NPOS + col0 + col];                        \
                v1 = M[(size_t)(x + 1) * NPOS + col0 + col];                  \
            } else {                                                          \
                v0 = F[(size_t)(x - 128) * NPOS + col0 + col];                \
                v1 = F[(size_t)(x - 127) * NPOS + col0 + col];                \
            }                                                                 \
            *(half2*)&smB[BUF][col * PB_H + (x - cc_)] = __floats2half2_rn(v0, v1); \
        }                                                                     \
    }                                                                         \
} while (0)

    GSTAGE(0, 0);
    __syncthreads();

    const int m0 = wm * 32;
    const int n0 = wn * 48;
    const int arow0 = lane >> 2;
    const int acol0 = lane & 3;
    const int brow0 = lane & 3;
    const int bcol0 = lane >> 2;

    for (int s = 0; s < 8; s++) {
        int buf = s & 1;
        if (s + 1 < 8) GSTAGE(s + 1, buf ^ 1);

        const __half* A_ = smA[buf];
        const __half* B_ = smB[buf];
#pragma unroll
        for (int k0 = 0; k0 < 32; k0 += 16) {
            uint32_t af[2][4];
#pragma unroll
            for (int mt = 0; mt < 2; mt++) {
                int r = m0 + mt * 16 + arow0;
                af[mt][0] = *(const uint32_t*)&A_[r * PA_H + k0 + 2 * acol0];
                af[mt][1] = *(const uint32_t*)&A_[(r + 8) * PA_H + k0 + 2 * acol0];
                af[mt][2] = *(const uint32_t*)&A_[r * PA_H + k0 + 2 * acol0 + 8];
                af[mt][3] = *(const uint32_t*)&A_[(r + 8) * PA_H + k0 + 2 * acol0 + 8];
            }
#pragma unroll
            for (int nt = 0; nt < 6; nt++) {
                int ncol = n0 + nt * 8 + bcol0;
                uint32_t bf[2];
                bf[0] = *(const uint32_t*)&B_[ncol * PB_H + k0 + 2 * brow0];
                bf[1] = *(const uint32_t*)&B_[ncol * PB_H + k0 + 2 * brow0 + 8];
                mma_f16(acc[0][nt], af[0], bf);
                mma_f16(acc[1][nt], af[1], bf);
            }
        }
        __syncthreads();
    }

    float* ob = (oblk == 0) ? (g_z + base) : (g_r + base);
#pragma unroll
    for (int mt = 0; mt < 2; mt++) {
#pragma unroll
        for (int half = 0; half < 2; half++) {
            int o = m0 + mt * 16 + half * 8 + (lane >> 2);
            float bv = __ldg(bias + o);
            float* orow = ob + (size_t)o * NPOS + col0;
#pragma unroll
            for (int nt = 0; nt < 6; nt++) {
                int col = n0 + nt * 8 + (lane & 3) * 2;
                orow[col]     = sigm(acc[mt][nt][half * 2 + 0] + bv);
                orow[col + 1] = sigm(acc[mt][nt][half * 2 + 1] + bv);
            }
        }
    }
#undef GSTAGE
}

// ---------------------------------------------------------------------------
// g3 via mma.sync fp16: cand = tanh(W2 @ [m; feat*r] + b2), fused GRU update
// ---------------------------------------------------------------------------
__global__ __launch_bounds__(256)
void g3_mma_kernel(float* __restrict__ dout, int it,
                   const float* __restrict__ gbR, const float* __restrict__ gbD,
                   const float* __restrict__ gamR, const float* __restrict__ gamD)
{
    __shared__ __half smA[2][A_BUF_H];
    __shared__ __half smB[2][B_BUF_H];

    const float* feat = it ? g_feat2 : dout;
    float* dst        = it ? dout : g_feat2;
    const int tid = threadIdx.x;
    const int lane = tid & 31;
    const int wid = tid >> 5;
    const int wm = wid & 3;
    const int wn = wid >> 2;

    const int zid = blockIdx.z;
    const int mod = zid >> 3, bn = zid & 7;
    const int col0 = blockIdx.x * 96;

    const __half* Agw = g_gwh + (size_t)mod * 3 * 128 * 256 + (size_t)2 * 128 * 256;
    const float* bias = (mod ? gbD : gbR) + 2 * 128;
    float gam = mod ? __ldg(gamD) : __ldg(gamR);
    size_t base = (size_t)(mod * 8 + bn) * 128 * NPOS;
    const float* F = feat + base;
    const float* M = g_m + base;
    const float* R = g_r + base;

    const int arow = tid >> 1;
    const int ahb  = (tid & 1) * 16;

    float acc[2][6][4];
#pragma unroll
    for (int i = 0; i < 2; i++)
#pragma unroll
        for (int j = 0; j < 6; j++)
#pragma unroll
            for (int k = 0; k < 4; k++) acc[i][j][k] = 0.f;

#define G3STAGE(S, BUF) do {                                                  \
    int cc_ = (S) * 32;                                                       \
    { const __half* wsrc = Agw + (size_t)arow * 256 + cc_ + ahb;              \
      uint4 v0 = *(const uint4*)(wsrc);                                       \
      uint4 v1 = *(const uint4*)(wsrc + 8);                                   \
      __half* ad = &smA[BUF][arow * PA_H + ahb];                              \
      *(uint4*)(ad) = v0; *(uint4*)(ad + 8) = v1; }                           \
    _Pragma("unroll")                                                         \
    for (int pb = 0; pb < 3; pb++) {                                          \
        int col = lane + 32 * pb;                                             \
        _Pragma("unroll")                                                     \
        for (int pp = 0; pp < 2; pp++) {                                      \
            int x = cc_ + 2 * (wid + 8 * pp);                                 \
            float v0, v1;                                                     \
            if (x < 128) {                                                    \
                v0 = M[(size_t)x * NPOS + col0 + col];                        \
                v1 = M[(size_t)(x + 1) * NPOS + col0 + col];                  \
            } else {                                                          \
                size_t i0 = (size_t)(x - 128) * NPOS + col0 + col;            \
                size_t i1 = (size_t)(x - 127) * NPOS + col0 + col;            \
                v0 = F[i0] * R[i0];                                           \
                v1 = F[i1] * R[i1];                                           \
            }                                                                 \
            *(half2*)&smB[BUF][col * PB_H + (x - cc_)] = __floats2half2_rn(v0, v1); \
        }                                                                     \
    }                                                                         \
} while (0)

    G3STAGE(0, 0);
    __syncthreads();

    const int m0 = wm * 32;
    const int n0 = wn * 48;
    const int arow0 = lane >> 2;
    const int acol0 = lane & 3;
    const int brow0 = lane & 3;
    const int bcol0 = lane >> 2;

    for (int s = 0; s < 8; s++) {
        int buf = s & 1;
        if (s + 1 < 8) G3STAGE(s + 1, buf ^ 1);

        const __half* A_ = smA[buf];
        const __half* B_ = smB[buf];
#pragma unroll
        for (int k0 = 0; k0 < 32; k0 += 16) {
            uint32_t af[2][4];
#pragma unroll
            for (int mt = 0; mt < 2; mt++) {
                int r = m0 + mt * 16 + arow0;
                af[mt][0] = *(const uint32_t*)&A_[r * PA_H + k0 + 2 * acol0];
                af[mt][1] = *(const uint32_t*)&A_[(r + 8) * PA_H + k0 + 2 * acol0];
                af[mt][2] = *(const uint32_t*)&A_[r * PA_H + k0 + 2 * acol0 + 8];
                af[mt][3] = *(const uint32_t*)&A_[(r + 8) * PA_H + k0 + 2 * acol0 + 8];
            }
#pragma unroll
            for (int nt = 0; nt < 6; nt++) {
                int ncol = n0 + nt * 8 + bcol0;
                uint32_t bf[2];
                bf[0] = *(const uint32_t*)&B_[ncol * PB_H + k0 + 2 * brow0];
                bf[1] = *(const uint32_t*)&B_[ncol * PB_H + k0 + 2 * brow0 + 8];
                mma_f16(acc[0][nt], af[0], bf);
                mma_f16(acc[1][nt], af[1], bf);
            }
        }
        __syncthreads();
    }

#pragma unroll
    for (int mt = 0; mt < 2; mt++) {
#pragma unroll
        for (int half = 0; half < 2; half++) {
            int o = m0 + mt * 16 + half * 8 + (lane >> 2);
            float bv = __ldg(bias + o);
#pragma unroll
            for (int nt = 0; nt < 6; nt++) {
                int col = col0 + n0 + nt * 8 + (lane & 3) * 2;
#pragma unroll
                for (int u = 0; u < 2; u++) {
                    size_t idx = base + (size_t)o * NPOS + col + u;
                    float cand = tanhf(acc[mt][nt][half * 2 + u] + bv);
                    float z = g_z[idx];
                    float f = feat[idx];
                    dst[idx] = fmaf(gam, fmaf(f, 1.f - z, cand * z), f);
                }
            }
        }
    }
#undef G3STAGE
}

// ---------------------------------------------------------------------------
extern "C" void kernel_launch(void* const* d_in, const int* in_sizes, int n_in,
                              void* d_out, int out_size)
{
    const float* feat_rgb = (const float*)d_in[0];
    const float* feat_dep = (const float*)d_in[1];
    const float* ppm_w_r  = (const float*)d_in[2];
    const float* ppm_s_r  = (const float*)d_in[3];
    const float* ppm_b_r  = (const float*)d_in[4];
    const float* ppm_w_d  = (const float*)d_in[5];
    const float* ppm_s_d  = (const float*)d_in[6];
    const float* ppm_b_d  = (const float*)d_in[7];
    const float* pa_w     = (const float*)d_in[8];
    const float* wgt_r    = (const float*)d_in[9];
    const float* gruw_r   = (const float*)d_in[10];
    const float* grub_r   = (const float*)d_in[11];
    const float* gam_r    = (const float*)d_in[12];
    const float* wgt_d    = (const float*)d_in[13];
    const float* gruw_d   = (const float*)d_in[14];
    const float* grub_d   = (const float*)d_in[15];
    const float* gam_d    = (const float*)d_in[16];
    float* out = (float*)d_out;

    wt_prep_kernel<<<(2*4*9*128*512 + 255) / 256, 256>>>(ppm_w_r, ppm_w_d);
    gwh_prep_kernel<<<(2*3*128*256 + 255) / 256, 256>>>(gruw_r, gruw_d);
    in_prep_kernel<<<(4*256*NPOS + 255) / 256, 256>>>(feat_rgb, feat_dep);
    conv_mma_kernel<<<dim3(48, 8), 256>>>(ppm_s_r, ppm_b_r, ppm_s_d, ppm_b_d, out);
    pa_kernel<<<288, 256>>>(out, pa_w);
    for (int it = 0; it < 2; it++) {
        g1a_kernel<<<dim3(36, 2, 2), 256>>>(out, it, wgt_r, wgt_d);
        g1b_kernel<<<dim3(1152, 2, 2), 256>>>(out, it);
        g2_mma_kernel<<<dim3(24, 2, 16), 256>>>(out, it, grub_r, grub_d);
        g3_mma_kernel<<<dim3(24, 1, 16), 256>>>(out, it, grub_r, grub_d,
                                                gam_r, gam_d);
    }
}